// round 13
// baseline (speedup 1.0000x reference)
#include <cuda_runtime.h>

#define NMAX 100000
#define EPS 1e-5f

typedef unsigned long long ull;

// ---------------- scratch ----------------
__device__ float g_buf_h[(size_t)NMAX * 64];   // h_raw (ReLU output, pre-BN)
__device__ float g_buf_m[(size_t)NMAX * 32];   // m_raw (pre-BN)
__device__ float g_agg  [(size_t)NMAX * 32];   // segment-sum of BN(m)
__device__ float g_buf_u[(size_t)NMAX * 64];   // u_raw
// [0:64) sum_h [64:128) sq_h [128:160) sum_m [192:224) sq_m [256:320) sum_u [320:384) sq_u
__device__ float g_stats[384];

// ---------------- f32x2 helpers ----------------
__device__ __forceinline__ void ffma2(ull &d, ull a, ull b) {
    asm("fma.rn.f32x2 %0, %1, %2, %0;" : "+l"(d) : "l"(a), "l"(b));
}
__device__ __forceinline__ ull dup2(float w) {
    ull r; unsigned u = __float_as_uint(w);
    asm("mov.b64 %0, {%1, %1};" : "=l"(r) : "r"(u)); return r;
}
__device__ __forceinline__ ull pack2(float lo, float hi) {
    ull r;
    asm("mov.b64 %0, {%1, %2};" : "=l"(r) : "r"(__float_as_uint(lo)), "r"(__float_as_uint(hi)));
    return r;
}
__device__ __forceinline__ float2 unp2(ull v) {
    unsigned lo, hi;
    asm("mov.b64 {%0, %1}, %2;" : "=r"(lo), "=r"(hi) : "l"(v));
    return make_float2(__uint_as_float(lo), __uint_as_float(hi));
}
__device__ __forceinline__ ull ldd(const float2* p) {
    return *reinterpret_cast<const ull*>(p);
}

// ---------------- K0: zero agg + stats ----------------
__global__ __launch_bounds__(256) void k_zero(int n4) {
    int t = blockIdx.x * 256 + threadIdx.x;
    float4 z = make_float4(0.f, 0.f, 0.f, 0.f);
    if (t < n4) reinterpret_cast<float4*>(g_agg)[t] = z;
    if (t < 384) g_stats[t] = 0.f;
}

// ---------------- K1 (frozen): h_raw = ReLU(nodes @ W_in + b), h stats ------------
__global__ __launch_bounds__(256) void k1_input(
    const float* __restrict__ nodes, const float* __restrict__ W,
    const float* __restrict__ b, int Nn)
{
    __shared__ float sWt[32 * 64];
    __shared__ ulonglong2 sX[32 * 17];
    __shared__ float rs[64], rq[64];
    int tid = threadIdx.x;
    for (int i = tid; i < 2048; i += 256) sWt[i] = W[i];
    if (tid < 64) { rs[tid] = 0.f; rq[tid] = 0.f; }
    int c = tid & 31, wp = tid >> 5;
    ull bl = dup2(b[c]), bh = dup2(b[c + 32]);
    float s0 = 0.f, q0 = 0.f, s1 = 0.f, q1 = 0.f;
    float* sXf = (float*)sX;

    for (int tile = blockIdx.x * 64; tile < Nn; tile += gridDim.x * 64) {
        __syncthreads();
        int cnt = Nn - tile; if (cnt > 64) cnt = 64;
        for (int i = tid; i < 64 * 32; i += 256) {
            int n = i >> 5, k = i & 31;
            float v = (n < cnt) ? nodes[(size_t)(tile + n) * 32 + k] : 0.f;
            sXf[(n >> 1) * 68 + k * 2 + (n & 1)] = v;
        }
        __syncthreads();

        ull a0[4], a1[4];
        #pragma unroll
        for (int p = 0; p < 4; p++) { a0[p] = bl; a1[p] = bh; }
        #pragma unroll
        for (int k2 = 0; k2 < 16; k2++) {
            int k = k2 * 2;
            ull w0 = dup2(sWt[k * 64 + c]);
            ull w1 = dup2(sWt[k * 64 + c + 32]);
            ull w2 = dup2(sWt[k * 64 + 64 + c]);
            ull w3 = dup2(sWt[k * 64 + 64 + c + 32]);
            #pragma unroll
            for (int p = 0; p < 4; p++) {
                ulonglong2 x = sX[(wp * 4 + p) * 17 + k2];
                ffma2(a0[p], x.x, w0); ffma2(a1[p], x.x, w1);
                ffma2(a0[p], x.y, w2); ffma2(a1[p], x.y, w3);
            }
        }
        #pragma unroll
        for (int p = 0; p < 4; p++) {
            float2 f0 = unp2(a0[p]), f1 = unp2(a1[p]);
            int n0 = tile + wp * 8 + 2 * p;
            float v;
            if (n0 < Nn) {
                v = fmaxf(f0.x, 0.f); g_buf_h[(size_t)n0 * 64 + c] = v;        s0 += v; q0 += v * v;
                v = fmaxf(f1.x, 0.f); g_buf_h[(size_t)n0 * 64 + c + 32] = v;   s1 += v; q1 += v * v;
            }
            if (n0 + 1 < Nn) {
                v = fmaxf(f0.y, 0.f); g_buf_h[(size_t)(n0 + 1) * 64 + c] = v;      s0 += v; q0 += v * v;
                v = fmaxf(f1.y, 0.f); g_buf_h[(size_t)(n0 + 1) * 64 + c + 32] = v; s1 += v; q1 += v * v;
            }
        }
    }
    __syncthreads();
    atomicAdd(&rs[c], s0);      atomicAdd(&rq[c], q0);
    atomicAdd(&rs[c + 32], s1); atomicAdd(&rq[c + 32], q1);
    __syncthreads();
    if (tid < 64) { atomicAdd(&g_stats[tid], rs[tid]); atomicAdd(&g_stats[64 + tid], rq[tid]); }
}

// ---------------- K2 (frozen): m_raw = ReLU(BN(h) @ W_msg + b), BN folded ---------
__global__ __launch_bounds__(256) void k2_msg(
    const float* __restrict__ Wm, const float* __restrict__ bm,
    const float* __restrict__ gam, const float* __restrict__ bet,
    int Nn, float invN)
{
    __shared__ float sWt[64 * 32];
    __shared__ ulonglong2 sH[32 * 33];
    __shared__ float sSc[64], sSh[64], sB[32];
    __shared__ float rs[32], rq[32];
    int tid = threadIdx.x;
    if (tid < 64) {
        float mean = g_stats[tid] * invN;
        float var  = fmaf(-mean, mean, g_stats[64 + tid] * invN);
        float r = rsqrtf(var + EPS);
        float s = gam[tid] * r;
        sSc[tid] = s; sSh[tid] = bet[tid] - mean * s;
    }
    if (tid < 32) { sB[tid] = bm[tid]; rs[tid] = 0.f; rq[tid] = 0.f; }
    __syncthreads();
    for (int i = tid; i < 2048; i += 256) sWt[i] = Wm[i] * sSc[i >> 5];
    {
        int cc = tid & 31, part = tid >> 5;
        float acc = 0.f;
        #pragma unroll
        for (int j = part * 8; j < part * 8 + 8; j++) acc += sSh[j] * Wm[j * 32 + cc];
        atomicAdd(&sB[cc], acc);
    }
    __syncthreads();
    int c = tid & 31, wp = tid >> 5;
    ull bl = dup2(sB[c]);
    float s0 = 0.f, q0 = 0.f;
    float* sHf = (float*)sH;

    for (int tile = blockIdx.x * 64; tile < Nn; tile += gridDim.x * 64) {
        __syncthreads();
        int cnt = Nn - tile; if (cnt > 64) cnt = 64;
        for (int i = tid; i < 64 * 64; i += 256) {
            int n = i >> 6, k = i & 63;
            float v = (n < cnt) ? g_buf_h[(size_t)(tile + n) * 64 + k] : 0.f;
            sHf[(n >> 1) * 132 + k * 2 + (n & 1)] = v;
        }
        __syncthreads();

        ull a[4];
        #pragma unroll
        for (int p = 0; p < 4; p++) a[p] = bl;
        #pragma unroll 8
        for (int k2 = 0; k2 < 32; k2++) {
            int k = k2 * 2;
            ull w0 = dup2(sWt[k * 32 + c]);
            ull w1 = dup2(sWt[k * 32 + 32 + c]);
            #pragma unroll
            for (int p = 0; p < 4; p++) {
                ulonglong2 x = sH[(wp * 4 + p) * 33 + k2];
                ffma2(a[p], x.x, w0); ffma2(a[p], x.y, w1);
            }
        }
        #pragma unroll
        for (int p = 0; p < 4; p++) {
            float2 f = unp2(a[p]);
            int n0 = tile + wp * 8 + 2 * p;
            if (n0 < Nn)     { float v = fmaxf(f.x, 0.f); g_buf_m[(size_t)n0 * 32 + c] = v;       s0 += v; q0 += v * v; }
            if (n0 + 1 < Nn) { float v = fmaxf(f.y, 0.f); g_buf_m[(size_t)(n0 + 1) * 32 + c] = v; s0 += v; q0 += v * v; }
        }
    }
    __syncthreads();
    atomicAdd(&rs[c], s0); atomicAdd(&rq[c], q0);
    __syncthreads();
    if (tid < 32) { atomicAdd(&g_stats[128 + tid], rs[tid]); atomicAdd(&g_stats[192 + tid], rq[tid]); }
}

// ---------------- K3 (frozen, ILP 8, at LTS ceiling): 8 edges / group --------------
__global__ __launch_bounds__(256) void k3_edges(
    const int* __restrict__ esrc, const int* __restrict__ edst,
    const float* __restrict__ gam, const float* __restrict__ bet,
    int E, float invN)
{
    __shared__ float sc[32], sh[32];
    if (threadIdx.x < 32) {
        int c = threadIdx.x;
        float mean = g_stats[128 + c] * invN;
        float var  = fmaf(-mean, mean, g_stats[192 + c] * invN);
        float r = rsqrtf(var + EPS);
        float s = gam[c] * r;
        sc[c] = s; sh[c] = bet[c] - mean * s;
    }
    __syncthreads();
    long long t = (long long)blockIdx.x * 256 + threadIdx.x;
    int g = (int)(t >> 3);
    int e0 = g * 8;
    if (e0 >= E) return;
    int j = (int)(t & 7);
    int c0 = j * 4;
    float scx = sc[c0], scy = sc[c0 + 1], scz = sc[c0 + 2], scw = sc[c0 + 3];
    float shx = sh[c0], shy = sh[c0 + 1], shz = sh[c0 + 2], shw = sh[c0 + 3];
    const float4* mp = (const float4*)g_buf_m;

    if (e0 + 8 <= E) {
        int4 sA = *(const int4*)(esrc + e0);
        int4 sB4 = *(const int4*)(esrc + e0 + 4);
        int4 dA = *(const int4*)(edst + e0);
        int4 dB = *(const int4*)(edst + e0 + 4);
        int ss[8] = {sA.x, sA.y, sA.z, sA.w, sB4.x, sB4.y, sB4.z, sB4.w};
        int dd[8] = {dA.x, dA.y, dA.z, dA.w, dB.x, dB.y, dB.z, dB.w};
        float4 v[8];
        #pragma unroll
        for (int i = 0; i < 8; i++) v[i] = __ldg(mp + (size_t)ss[i] * 8 + j);
        #pragma unroll
        for (int i = 0; i < 8; i++) {
            float x = fmaf(v[i].x, scx, shx), y = fmaf(v[i].y, scy, shy);
            float z = fmaf(v[i].z, scz, shz), w = fmaf(v[i].w, scw, shw);
            float* p = g_agg + (size_t)dd[i] * 32 + c0;
            asm volatile("red.global.add.v4.f32 [%0], {%1,%2,%3,%4};"
                         :: "l"(p), "f"(x), "f"(y), "f"(z), "f"(w) : "memory");
        }
    } else {
        for (int e = e0; e < E; e++) {
            int s = esrc[e], d = edst[e];
            float4 v = __ldg(mp + (size_t)s * 8 + j);
            float x = fmaf(v.x, scx, shx), y = fmaf(v.y, scy, shy);
            float z = fmaf(v.z, scz, shz), w = fmaf(v.w, scw, shw);
            float* p = g_agg + (size_t)d * 32 + c0;
            asm volatile("red.global.add.v4.f32 [%0], {%1,%2,%3,%4};"
                         :: "l"(p), "f"(x), "f"(y), "f"(z), "f"(w) : "memory");
        }
    }
}

// ---------------- K4 (frozen, local optimum ~60us): 64-node tile, p=8 --------------
__global__ __launch_bounds__(256) void k4_update(
    const float* __restrict__ goal, const float* __restrict__ Wu,
    const float* __restrict__ bu, const float* __restrict__ gam,
    const float* __restrict__ bet, int Nn, float invN)
{
    __shared__ __align__(16) float2 sW2[56 * 64];   // 28 KB folded, k-paired
    __shared__ __align__(16) float  sX[64 * 112];   // 28 KB node-major concat
    __shared__ float sSc[64], sSh[64], sB[64];
    __shared__ float rs[64], rq[64];
    int tid = threadIdx.x;
    if (tid < 64) {
        float mean = g_stats[tid] * invN;
        float var  = fmaf(-mean, mean, g_stats[64 + tid] * invN);
        float r = rsqrtf(var + EPS);
        float s = gam[tid] * r;
        sSc[tid] = s; sSh[tid] = bet[tid] - mean * s;
        sB[tid] = bu[tid]; rs[tid] = 0.f; rq[tid] = 0.f;
    }
    __syncthreads();
    {
        float* sWf = (float*)sW2;
        for (int i = tid; i < 112 * 64; i += 256) {
            int k = i >> 6, cc = i & 63;
            float f = (k >= 32 && k < 96) ? sSc[k - 32] : 1.f;
            sWf[(k >> 1) * 128 + cc * 2 + (k & 1)] = Wu[i] * f;
        }
        int cc = tid & 63, part = tid >> 6;
        float acc = 0.f;
        #pragma unroll
        for (int j = part * 16; j < part * 16 + 16; j++) acc += sSh[j] * Wu[(32 + j) * 64 + cc];
        atomicAdd(&sB[cc], acc);
    }
    __syncthreads();
    int c = tid & 31, wp = tid >> 5;
    float bl = sB[c], bh = sB[c + 32];
    float s0 = 0.f, q0 = 0.f, s1 = 0.f, q1 = 0.f;
    float4* sX4 = (float4*)sX;
    const float4* ap = (const float4*)g_agg;
    const float4* hp = (const float4*)g_buf_h;
    const float4* gp = (const float4*)goal;
    float4 z4 = make_float4(0.f, 0.f, 0.f, 0.f);

    for (int tile = blockIdx.x * 64; tile < Nn; tile += gridDim.x * 64) {
        __syncthreads();
        #pragma unroll
        for (int it = 0; it < 7; it++) {
            int f = tid + it * 256;            // 0..1791; row = 28 float4
            int n = f / 28, r = f - n * 28;
            int gn = tile + n;
            float4 v = z4;
            if (gn < Nn) {
                v = (r < 8)  ? ap[(size_t)gn * 8 + r]
                  : (r < 24) ? hp[(size_t)gn * 16 + (r - 8)]
                             : gp[(size_t)gn * 4 + (r - 24)];
            }
            sX4[f] = v;
        }
        __syncthreads();

        ull a0[8], a1[8];
        #pragma unroll
        for (int p = 0; p < 8; p++) { a0[p] = pack2(bl, 0.f); a1[p] = pack2(bh, 0.f); }
        const ulonglong2* xp = (const ulonglong2*)(sX + (size_t)(wp * 8) * 112);
        #pragma unroll 4
        for (int kq = 0; kq < 28; kq++) {
            ull w00 = ldd(&sW2[(2 * kq) * 64 + c]);
            ull w01 = ldd(&sW2[(2 * kq) * 64 + c + 32]);
            ull w10 = ldd(&sW2[(2 * kq + 1) * 64 + c]);
            ull w11 = ldd(&sW2[(2 * kq + 1) * 64 + c + 32]);
            #pragma unroll
            for (int p = 0; p < 8; p++) {
                ulonglong2 x = xp[p * 28 + kq];
                ffma2(a0[p], x.x, w00); ffma2(a1[p], x.x, w01);
                ffma2(a0[p], x.y, w10); ffma2(a1[p], x.y, w11);
            }
        }
        #pragma unroll
        for (int p = 0; p < 8; p++) {
            int gn = tile + wp * 8 + p;
            if (gn < Nn) {
                float2 f0 = unp2(a0[p]), f1 = unp2(a1[p]);
                float v0 = fmaxf(f0.x + f0.y, 0.f), v1 = fmaxf(f1.x + f1.y, 0.f);
                g_buf_u[(size_t)gn * 64 + c]      = v0; s0 += v0; q0 += v0 * v0;
                g_buf_u[(size_t)gn * 64 + c + 32] = v1; s1 += v1; q1 += v1 * v1;
            }
        }
    }
    __syncthreads();
    atomicAdd(&rs[c], s0);      atomicAdd(&rq[c], q0);
    atomicAdd(&rs[c + 32], s1); atomicAdd(&rq[c + 32], q1);
    __syncthreads();
    if (tid < 64) { atomicAdd(&g_stats[256 + tid], rs[tid]); atomicAdd(&g_stats[320 + tid], rq[tid]); }
}

// ---------------- K5 (R2 + vectorized phase 2): u = BN(u_raw); out = u @ W_out ----
__global__ __launch_bounds__(256) void k5_output(
    const float* __restrict__ Wo, const float* __restrict__ bo,
    const float* __restrict__ gam, const float* __restrict__ bet,
    float* __restrict__ out_u, float* __restrict__ out_o,
    int Nn, float invN)
{
    __shared__ __align__(16) float sWt[8 * 64];   // transposed [oc][k]
    __shared__ __align__(16) float sU[4 * 68];    // stride 68 -> 16B-aligned rows
    __shared__ float sScale[64], sShift[64];
    int tid = threadIdx.x;
    for (int i = tid; i < 512; i += 256) {
        int k = i >> 3, oc = i & 7;
        sWt[oc * 64 + k] = Wo[i];
    }
    if (tid < 64) {
        float mean = g_stats[256 + tid] * invN;
        float var  = fmaf(-mean, mean, g_stats[320 + tid] * invN);
        float r    = rsqrtf(var + EPS);
        float sc   = gam[tid] * r;
        sScale[tid] = sc; sShift[tid] = bet[tid] - mean * sc;
    }
    int c = tid & 63, l = tid >> 6;

    for (int base = blockIdx.x * 4; base < Nn; base += gridDim.x * 4) {
        __syncthreads();
        int n = base + l;
        float u = 0.f;
        if (n < Nn) {
            u = fmaf(g_buf_u[(size_t)n * 64 + c], sScale[c], sShift[c]);
            out_u[(size_t)n * 64 + c] = u;
        }
        sU[l * 68 + c] = u;
        __syncthreads();
        if (tid < 32) {
            int ln = tid >> 3, oc = tid & 7;
            int nn = base + ln;
            if (nn < Nn) {
                float acc = bo[oc];
                #pragma unroll
                for (int kk = 0; kk < 16; kk++) {
                    float4 uv = *reinterpret_cast<const float4*>(&sU[ln * 68 + kk * 4]);
                    float4 wv = *reinterpret_cast<const float4*>(&sWt[oc * 64 + kk * 4]);
                    acc = fmaf(uv.x, wv.x, acc); acc = fmaf(uv.y, wv.y, acc);
                    acc = fmaf(uv.z, wv.z, acc); acc = fmaf(uv.w, wv.w, acc);
                }
                out_o[(size_t)nn * 8 + oc] = acc;
            }
        }
    }
}

// ---------------- host launcher ----------------
extern "C" void kernel_launch(void* const* d_in, const int* in_sizes, int n_in,
                              void* d_out, int out_size)
{
    const float* nodes  = (const float*)d_in[0];
    const float* goal   = (const float*)d_in[1];
    const int*   esrc   = (const int*)d_in[2];
    const int*   edst   = (const int*)d_in[3];
    const float* W_in   = (const float*)d_in[6];
    const float* b_in   = (const float*)d_in[7];
    const float* g_in   = (const float*)d_in[8];
    const float* be_in  = (const float*)d_in[9];
    const float* W_msg  = (const float*)d_in[10];
    const float* b_msg  = (const float*)d_in[11];
    const float* g_msg  = (const float*)d_in[12];
    const float* be_msg = (const float*)d_in[13];
    const float* W_upd  = (const float*)d_in[14];
    const float* b_upd  = (const float*)d_in[15];
    const float* g_upd  = (const float*)d_in[16];
    const float* be_upd = (const float*)d_in[17];
    const float* W_out  = (const float*)d_in[18];
    const float* b_out  = (const float*)d_in[19];

    int N = in_sizes[0] / 32;
    int E = in_sizes[2];
    float invN = 1.0f / (float)N;

    float* dout = (float*)d_out;
    float* out_u;
    float* out_o;
    if ((long long)out_size >= (long long)N * 72) {        // tuple (u, out) concatenated
        out_u = dout;
        out_o = dout + (size_t)N * 64;
    } else if ((long long)out_size == (long long)N * 8) {  // only `out`
        void* p; cudaGetSymbolAddress(&p, g_buf_h);
        out_u = (float*)p;  out_o = dout;
    } else {                                               // only `u`
        void* p; cudaGetSymbolAddress(&p, g_buf_h);
        out_u = dout;       out_o = (float*)p;
    }

    int n4 = N * 8;   // N*32/4 float4s of agg
    k_zero  <<<(n4 + 255) / 256, 256>>>(n4);
    k1_input<<<592, 256>>>(nodes, W_in, b_in, N);
    k2_msg  <<<592, 256>>>(W_msg, b_msg, g_in, be_in, N, invN);
    long long groups = ((long long)E + 7) / 8;
    long long thr = groups * 8;
    k3_edges<<<(int)((thr + 255) / 256), 256>>>(esrc, edst, g_msg, be_msg, E, invN);
    k4_update<<<444, 256>>>(goal, W_upd, b_upd, g_in, be_in, N, invN);
    k5_output<<<2960, 256>>>(W_out, b_out, g_upd, be_upd, out_u, out_o, N, invN);
}

// round 14
// speedup vs baseline: 1.2632x; 1.2632x over previous
#include <cuda_runtime.h>

#define NMAX 100000
#define EPS 1e-5f

typedef unsigned long long ull;

// ---------------- scratch ----------------
__device__ float g_buf_h[(size_t)NMAX * 64];   // h_raw (ReLU output, pre-BN)
__device__ float g_buf_m[(size_t)NMAX * 32];   // m_raw (pre-BN)
__device__ float g_agg  [(size_t)NMAX * 32];   // segment-sum of BN(m)
__device__ float g_buf_u[(size_t)NMAX * 64];   // u_raw
// [0:64) sum_h [64:128) sq_h [128:160) sum_m [192:224) sq_m [256:320) sum_u [320:384) sq_u
__device__ float g_stats[384];

// ---------------- f32x2 helpers ----------------
__device__ __forceinline__ void ffma2(ull &d, ull a, ull b) {
    asm("fma.rn.f32x2 %0, %1, %2, %0;" : "+l"(d) : "l"(a), "l"(b));
}
__device__ __forceinline__ ull dup2(float w) {
    ull r; unsigned u = __float_as_uint(w);
    asm("mov.b64 %0, {%1, %1};" : "=l"(r) : "r"(u)); return r;
}
__device__ __forceinline__ ull pack2(float lo, float hi) {
    ull r;
    asm("mov.b64 %0, {%1, %2};" : "=l"(r) : "r"(__float_as_uint(lo)), "r"(__float_as_uint(hi)));
    return r;
}
__device__ __forceinline__ float2 unp2(ull v) {
    unsigned lo, hi;
    asm("mov.b64 {%0, %1}, %2;" : "=r"(lo), "=r"(hi) : "l"(v));
    return make_float2(__uint_as_float(lo), __uint_as_float(hi));
}
__device__ __forceinline__ ull ldd(const float2* p) {
    return *reinterpret_cast<const ull*>(p);
}

// ---------------- K0: zero agg + stats ----------------
__global__ __launch_bounds__(256) void k_zero(int n4) {
    int t = blockIdx.x * 256 + threadIdx.x;
    float4 z = make_float4(0.f, 0.f, 0.f, 0.f);
    if (t < n4) reinterpret_cast<float4*>(g_agg)[t] = z;
    if (t < 384) g_stats[t] = 0.f;
}

// ---------------- K1 (frozen): h_raw = ReLU(nodes @ W_in + b), h stats ------------
__global__ __launch_bounds__(256) void k1_input(
    const float* __restrict__ nodes, const float* __restrict__ W,
    const float* __restrict__ b, int Nn)
{
    __shared__ float sWt[32 * 64];
    __shared__ ulonglong2 sX[32 * 17];
    __shared__ float rs[64], rq[64];
    int tid = threadIdx.x;
    for (int i = tid; i < 2048; i += 256) sWt[i] = W[i];
    if (tid < 64) { rs[tid] = 0.f; rq[tid] = 0.f; }
    int c = tid & 31, wp = tid >> 5;
    ull bl = dup2(b[c]), bh = dup2(b[c + 32]);
    float s0 = 0.f, q0 = 0.f, s1 = 0.f, q1 = 0.f;
    float* sXf = (float*)sX;

    for (int tile = blockIdx.x * 64; tile < Nn; tile += gridDim.x * 64) {
        __syncthreads();
        int cnt = Nn - tile; if (cnt > 64) cnt = 64;
        for (int i = tid; i < 64 * 32; i += 256) {
            int n = i >> 5, k = i & 31;
            float v = (n < cnt) ? nodes[(size_t)(tile + n) * 32 + k] : 0.f;
            sXf[(n >> 1) * 68 + k * 2 + (n & 1)] = v;
        }
        __syncthreads();

        ull a0[4], a1[4];
        #pragma unroll
        for (int p = 0; p < 4; p++) { a0[p] = bl; a1[p] = bh; }
        #pragma unroll
        for (int k2 = 0; k2 < 16; k2++) {
            int k = k2 * 2;
            ull w0 = dup2(sWt[k * 64 + c]);
            ull w1 = dup2(sWt[k * 64 + c + 32]);
            ull w2 = dup2(sWt[k * 64 + 64 + c]);
            ull w3 = dup2(sWt[k * 64 + 64 + c + 32]);
            #pragma unroll
            for (int p = 0; p < 4; p++) {
                ulonglong2 x = sX[(wp * 4 + p) * 17 + k2];
                ffma2(a0[p], x.x, w0); ffma2(a1[p], x.x, w1);
                ffma2(a0[p], x.y, w2); ffma2(a1[p], x.y, w3);
            }
        }
        #pragma unroll
        for (int p = 0; p < 4; p++) {
            float2 f0 = unp2(a0[p]), f1 = unp2(a1[p]);
            int n0 = tile + wp * 8 + 2 * p;
            float v;
            if (n0 < Nn) {
                v = fmaxf(f0.x, 0.f); g_buf_h[(size_t)n0 * 64 + c] = v;        s0 += v; q0 += v * v;
                v = fmaxf(f1.x, 0.f); g_buf_h[(size_t)n0 * 64 + c + 32] = v;   s1 += v; q1 += v * v;
            }
            if (n0 + 1 < Nn) {
                v = fmaxf(f0.y, 0.f); g_buf_h[(size_t)(n0 + 1) * 64 + c] = v;      s0 += v; q0 += v * v;
                v = fmaxf(f1.y, 0.f); g_buf_h[(size_t)(n0 + 1) * 64 + c + 32] = v; s1 += v; q1 += v * v;
            }
        }
    }
    __syncthreads();
    atomicAdd(&rs[c], s0);      atomicAdd(&rq[c], q0);
    atomicAdd(&rs[c + 32], s1); atomicAdd(&rq[c + 32], q1);
    __syncthreads();
    if (tid < 64) { atomicAdd(&g_stats[tid], rs[tid]); atomicAdd(&g_stats[64 + tid], rq[tid]); }
}

// ---------------- K2 (frozen): m_raw = ReLU(BN(h) @ W_msg + b), BN folded ---------
__global__ __launch_bounds__(256) void k2_msg(
    const float* __restrict__ Wm, const float* __restrict__ bm,
    const float* __restrict__ gam, const float* __restrict__ bet,
    int Nn, float invN)
{
    __shared__ float sWt[64 * 32];
    __shared__ ulonglong2 sH[32 * 33];
    __shared__ float sSc[64], sSh[64], sB[32];
    __shared__ float rs[32], rq[32];
    int tid = threadIdx.x;
    if (tid < 64) {
        float mean = g_stats[tid] * invN;
        float var  = fmaf(-mean, mean, g_stats[64 + tid] * invN);
        float r = rsqrtf(var + EPS);
        float s = gam[tid] * r;
        sSc[tid] = s; sSh[tid] = bet[tid] - mean * s;
    }
    if (tid < 32) { sB[tid] = bm[tid]; rs[tid] = 0.f; rq[tid] = 0.f; }
    __syncthreads();
    for (int i = tid; i < 2048; i += 256) sWt[i] = Wm[i] * sSc[i >> 5];
    {
        int cc = tid & 31, part = tid >> 5;
        float acc = 0.f;
        #pragma unroll
        for (int j = part * 8; j < part * 8 + 8; j++) acc += sSh[j] * Wm[j * 32 + cc];
        atomicAdd(&sB[cc], acc);
    }
    __syncthreads();
    int c = tid & 31, wp = tid >> 5;
    ull bl = dup2(sB[c]);
    float s0 = 0.f, q0 = 0.f;
    float* sHf = (float*)sH;

    for (int tile = blockIdx.x * 64; tile < Nn; tile += gridDim.x * 64) {
        __syncthreads();
        int cnt = Nn - tile; if (cnt > 64) cnt = 64;
        for (int i = tid; i < 64 * 64; i += 256) {
            int n = i >> 6, k = i & 63;
            float v = (n < cnt) ? g_buf_h[(size_t)(tile + n) * 64 + k] : 0.f;
            sHf[(n >> 1) * 132 + k * 2 + (n & 1)] = v;
        }
        __syncthreads();

        ull a[4];
        #pragma unroll
        for (int p = 0; p < 4; p++) a[p] = bl;
        #pragma unroll 8
        for (int k2 = 0; k2 < 32; k2++) {
            int k = k2 * 2;
            ull w0 = dup2(sWt[k * 32 + c]);
            ull w1 = dup2(sWt[k * 32 + 32 + c]);
            #pragma unroll
            for (int p = 0; p < 4; p++) {
                ulonglong2 x = sH[(wp * 4 + p) * 33 + k2];
                ffma2(a[p], x.x, w0); ffma2(a[p], x.y, w1);
            }
        }
        #pragma unroll
        for (int p = 0; p < 4; p++) {
            float2 f = unp2(a[p]);
            int n0 = tile + wp * 8 + 2 * p;
            if (n0 < Nn)     { float v = fmaxf(f.x, 0.f); g_buf_m[(size_t)n0 * 32 + c] = v;       s0 += v; q0 += v * v; }
            if (n0 + 1 < Nn) { float v = fmaxf(f.y, 0.f); g_buf_m[(size_t)(n0 + 1) * 32 + c] = v; s0 += v; q0 += v * v; }
        }
    }
    __syncthreads();
    atomicAdd(&rs[c], s0); atomicAdd(&rq[c], q0);
    __syncthreads();
    if (tid < 32) { atomicAdd(&g_stats[128 + tid], rs[tid]); atomicAdd(&g_stats[192 + tid], rq[tid]); }
}

// ---------------- K3 (frozen, ILP 8, at LTS ceiling): 8 edges / group --------------
__global__ __launch_bounds__(256) void k3_edges(
    const int* __restrict__ esrc, const int* __restrict__ edst,
    const float* __restrict__ gam, const float* __restrict__ bet,
    int E, float invN)
{
    __shared__ float sc[32], sh[32];
    if (threadIdx.x < 32) {
        int c = threadIdx.x;
        float mean = g_stats[128 + c] * invN;
        float var  = fmaf(-mean, mean, g_stats[192 + c] * invN);
        float r = rsqrtf(var + EPS);
        float s = gam[c] * r;
        sc[c] = s; sh[c] = bet[c] - mean * s;
    }
    __syncthreads();
    long long t = (long long)blockIdx.x * 256 + threadIdx.x;
    int g = (int)(t >> 3);
    int e0 = g * 8;
    if (e0 >= E) return;
    int j = (int)(t & 7);
    int c0 = j * 4;
    float scx = sc[c0], scy = sc[c0 + 1], scz = sc[c0 + 2], scw = sc[c0 + 3];
    float shx = sh[c0], shy = sh[c0 + 1], shz = sh[c0 + 2], shw = sh[c0 + 3];
    const float4* mp = (const float4*)g_buf_m;

    if (e0 + 8 <= E) {
        int4 sA = *(const int4*)(esrc + e0);
        int4 sB4 = *(const int4*)(esrc + e0 + 4);
        int4 dA = *(const int4*)(edst + e0);
        int4 dB = *(const int4*)(edst + e0 + 4);
        int ss[8] = {sA.x, sA.y, sA.z, sA.w, sB4.x, sB4.y, sB4.z, sB4.w};
        int dd[8] = {dA.x, dA.y, dA.z, dA.w, dB.x, dB.y, dB.z, dB.w};
        float4 v[8];
        #pragma unroll
        for (int i = 0; i < 8; i++) v[i] = __ldg(mp + (size_t)ss[i] * 8 + j);
        #pragma unroll
        for (int i = 0; i < 8; i++) {
            float x = fmaf(v[i].x, scx, shx), y = fmaf(v[i].y, scy, shy);
            float z = fmaf(v[i].z, scz, shz), w = fmaf(v[i].w, scw, shw);
            float* p = g_agg + (size_t)dd[i] * 32 + c0;
            asm volatile("red.global.add.v4.f32 [%0], {%1,%2,%3,%4};"
                         :: "l"(p), "f"(x), "f"(y), "f"(z), "f"(w) : "memory");
        }
    } else {
        for (int e = e0; e < E; e++) {
            int s = esrc[e], d = edst[e];
            float4 v = __ldg(mp + (size_t)s * 8 + j);
            float x = fmaf(v.x, scx, shx), y = fmaf(v.y, scy, shy);
            float z = fmaf(v.z, scz, shz), w = fmaf(v.w, scw, shw);
            float* p = g_agg + (size_t)d * 32 + c0;
            asm volatile("red.global.add.v4.f32 [%0], {%1,%2,%3,%4};"
                         :: "l"(p), "f"(x), "f"(y), "f"(z), "f"(w) : "memory");
        }
    }
}

// ---------------- K4 (frozen, local optimum ~60us): 64-node tile, p=8 --------------
__global__ __launch_bounds__(256) void k4_update(
    const float* __restrict__ goal, const float* __restrict__ Wu,
    const float* __restrict__ bu, const float* __restrict__ gam,
    const float* __restrict__ bet, int Nn, float invN)
{
    __shared__ __align__(16) float2 sW2[56 * 64];   // 28 KB folded, k-paired
    __shared__ __align__(16) float  sX[64 * 112];   // 28 KB node-major concat
    __shared__ float sSc[64], sSh[64], sB[64];
    __shared__ float rs[64], rq[64];
    int tid = threadIdx.x;
    if (tid < 64) {
        float mean = g_stats[tid] * invN;
        float var  = fmaf(-mean, mean, g_stats[64 + tid] * invN);
        float r = rsqrtf(var + EPS);
        float s = gam[tid] * r;
        sSc[tid] = s; sSh[tid] = bet[tid] - mean * s;
        sB[tid] = bu[tid]; rs[tid] = 0.f; rq[tid] = 0.f;
    }
    __syncthreads();
    {
        float* sWf = (float*)sW2;
        for (int i = tid; i < 112 * 64; i += 256) {
            int k = i >> 6, cc = i & 63;
            float f = (k >= 32 && k < 96) ? sSc[k - 32] : 1.f;
            sWf[(k >> 1) * 128 + cc * 2 + (k & 1)] = Wu[i] * f;
        }
        int cc = tid & 63, part = tid >> 6;
        float acc = 0.f;
        #pragma unroll
        for (int j = part * 16; j < part * 16 + 16; j++) acc += sSh[j] * Wu[(32 + j) * 64 + cc];
        atomicAdd(&sB[cc], acc);
    }
    __syncthreads();
    int c = tid & 31, wp = tid >> 5;
    float bl = sB[c], bh = sB[c + 32];
    float s0 = 0.f, q0 = 0.f, s1 = 0.f, q1 = 0.f;
    float4* sX4 = (float4*)sX;
    const float4* ap = (const float4*)g_agg;
    const float4* hp = (const float4*)g_buf_h;
    const float4* gp = (const float4*)goal;
    float4 z4 = make_float4(0.f, 0.f, 0.f, 0.f);

    for (int tile = blockIdx.x * 64; tile < Nn; tile += gridDim.x * 64) {
        __syncthreads();
        #pragma unroll
        for (int it = 0; it < 7; it++) {
            int f = tid + it * 256;            // 0..1791; row = 28 float4
            int n = f / 28, r = f - n * 28;
            int gn = tile + n;
            float4 v = z4;
            if (gn < Nn) {
                v = (r < 8)  ? ap[(size_t)gn * 8 + r]
                  : (r < 24) ? hp[(size_t)gn * 16 + (r - 8)]
                             : gp[(size_t)gn * 4 + (r - 24)];
            }
            sX4[f] = v;
        }
        __syncthreads();

        ull a0[8], a1[8];
        #pragma unroll
        for (int p = 0; p < 8; p++) { a0[p] = pack2(bl, 0.f); a1[p] = pack2(bh, 0.f); }
        const ulonglong2* xp = (const ulonglong2*)(sX + (size_t)(wp * 8) * 112);
        #pragma unroll 4
        for (int kq = 0; kq < 28; kq++) {
            ull w00 = ldd(&sW2[(2 * kq) * 64 + c]);
            ull w01 = ldd(&sW2[(2 * kq) * 64 + c + 32]);
            ull w10 = ldd(&sW2[(2 * kq + 1) * 64 + c]);
            ull w11 = ldd(&sW2[(2 * kq + 1) * 64 + c + 32]);
            #pragma unroll
            for (int p = 0; p < 8; p++) {
                ulonglong2 x = xp[p * 28 + kq];
                ffma2(a0[p], x.x, w00); ffma2(a1[p], x.x, w01);
                ffma2(a0[p], x.y, w10); ffma2(a1[p], x.y, w11);
            }
        }
        #pragma unroll
        for (int p = 0; p < 8; p++) {
            int gn = tile + wp * 8 + p;
            if (gn < Nn) {
                float2 f0 = unp2(a0[p]), f1 = unp2(a1[p]);
                float v0 = fmaxf(f0.x + f0.y, 0.f), v1 = fmaxf(f1.x + f1.y, 0.f);
                g_buf_u[(size_t)gn * 64 + c]      = v0; s0 += v0; q0 += v0 * v0;
                g_buf_u[(size_t)gn * 64 + c + 32] = v1; s1 += v1; q1 += v1 * v1;
            }
        }
    }
    __syncthreads();
    atomicAdd(&rs[c], s0);      atomicAdd(&rq[c], q0);
    atomicAdd(&rs[c + 32], s1); atomicAdd(&rq[c + 32], q1);
    __syncthreads();
    if (tid < 64) { atomicAdd(&g_stats[256 + tid], rs[tid]); atomicAdd(&g_stats[320 + tid], rq[tid]); }
}

// ---------------- K5 (vectorized, bank-conflict-FIXED weight stride 68) ------------
__global__ __launch_bounds__(256) void k5_output(
    const float* __restrict__ Wo, const float* __restrict__ bo,
    const float* __restrict__ gam, const float* __restrict__ bet,
    float* __restrict__ out_u, float* __restrict__ out_o,
    int Nn, float invN)
{
    __shared__ __align__(16) float sWt[8 * 68];   // transposed [oc][k], stride 68
                                                  // row start bank = 4*oc -> conflict-free
    __shared__ __align__(16) float sU[4 * 68];    // stride 68 -> 16B-aligned rows
    __shared__ float sScale[64], sShift[64];
    int tid = threadIdx.x;
    for (int i = tid; i < 512; i += 256) {
        int k = i >> 3, oc = i & 7;
        sWt[oc * 68 + k] = Wo[i];
    }
    if (tid < 64) {
        float mean = g_stats[256 + tid] * invN;
        float var  = fmaf(-mean, mean, g_stats[320 + tid] * invN);
        float r    = rsqrtf(var + EPS);
        float sc   = gam[tid] * r;
        sScale[tid] = sc; sShift[tid] = bet[tid] - mean * sc;
    }
    int c = tid & 63, l = tid >> 6;

    for (int base = blockIdx.x * 4; base < Nn; base += gridDim.x * 4) {
        __syncthreads();
        int n = base + l;
        float u = 0.f;
        if (n < Nn) {
            u = fmaf(g_buf_u[(size_t)n * 64 + c], sScale[c], sShift[c]);
            out_u[(size_t)n * 64 + c] = u;
        }
        sU[l * 68 + c] = u;
        __syncthreads();
        if (tid < 32) {
            int ln = tid >> 3, oc = tid & 7;
            int nn = base + ln;
            if (nn < Nn) {
                float acc = bo[oc];
                #pragma unroll
                for (int kk = 0; kk < 16; kk++) {
                    float4 uv = *reinterpret_cast<const float4*>(&sU[ln * 68 + kk * 4]);
                    float4 wv = *reinterpret_cast<const float4*>(&sWt[oc * 68 + kk * 4]);
                    acc = fmaf(uv.x, wv.x, acc); acc = fmaf(uv.y, wv.y, acc);
                    acc = fmaf(uv.z, wv.z, acc); acc = fmaf(uv.w, wv.w, acc);
                }
                out_o[(size_t)nn * 8 + oc] = acc;
            }
        }
    }
}

// ---------------- host launcher ----------------
extern "C" void kernel_launch(void* const* d_in, const int* in_sizes, int n_in,
                              void* d_out, int out_size)
{
    const float* nodes  = (const float*)d_in[0];
    const float* goal   = (const float*)d_in[1];
    const int*   esrc   = (const int*)d_in[2];
    const int*   edst   = (const int*)d_in[3];
    const float* W_in   = (const float*)d_in[6];
    const float* b_in   = (const float*)d_in[7];
    const float* g_in   = (const float*)d_in[8];
    const float* be_in  = (const float*)d_in[9];
    const float* W_msg  = (const float*)d_in[10];
    const float* b_msg  = (const float*)d_in[11];
    const float* g_msg  = (const float*)d_in[12];
    const float* be_msg = (const float*)d_in[13];
    const float* W_upd  = (const float*)d_in[14];
    const float* b_upd  = (const float*)d_in[15];
    const float* g_upd  = (const float*)d_in[16];
    const float* be_upd = (const float*)d_in[17];
    const float* W_out  = (const float*)d_in[18];
    const float* b_out  = (const float*)d_in[19];

    int N = in_sizes[0] / 32;
    int E = in_sizes[2];
    float invN = 1.0f / (float)N;

    float* dout = (float*)d_out;
    float* out_u;
    float* out_o;
    if ((long long)out_size >= (long long)N * 72) {        // tuple (u, out) concatenated
        out_u = dout;
        out_o = dout + (size_t)N * 64;
    } else if ((long long)out_size == (long long)N * 8) {  // only `out`
        void* p; cudaGetSymbolAddress(&p, g_buf_h);
        out_u = (float*)p;  out_o = dout;
    } else {                                               // only `u`
        void* p; cudaGetSymbolAddress(&p, g_buf_h);
        out_u = dout;       out_o = (float*)p;
    }

    int n4 = N * 8;   // N*32/4 float4s of agg
    k_zero  <<<(n4 + 255) / 256, 256>>>(n4);
    k1_input<<<592, 256>>>(nodes, W_in, b_in, N);
    k2_msg  <<<592, 256>>>(W_msg, b_msg, g_in, be_in, N, invN);
    long long groups = ((long long)E + 7) / 8;
    long long thr = groups * 8;
    k3_edges<<<(int)((thr + 255) / 256), 256>>>(esrc, edst, g_msg, be_msg, E, invN);
    k4_update<<<444, 256>>>(goal, W_upd, b_upd, g_in, be_in, N, invN);
    k5_output<<<2960, 256>>>(W_out, b_out, g_upd, be_upd, out_u, out_o, N, invN);
}

// round 15
// speedup vs baseline: 1.3167x; 1.0423x over previous
#include <cuda_runtime.h>

#define NMAX 100000
#define EPS 1e-5f

typedef unsigned long long ull;

// ---------------- scratch ----------------
__device__ float g_buf_h[(size_t)NMAX * 64];   // h_raw (ReLU output, pre-BN)
__device__ float g_buf_m[(size_t)NMAX * 32];   // m_raw (pre-BN)
__device__ float g_agg  [(size_t)NMAX * 32];   // segment-sum of BN(m)
__device__ float g_buf_u[(size_t)NMAX * 64];   // u_raw
// [0:64) sum_h [64:128) sq_h [128:160) sum_m [192:224) sq_m [256:320) sum_u [320:384) sq_u
__device__ float g_stats[384];

// ---------------- f32x2 helpers ----------------
__device__ __forceinline__ void ffma2(ull &d, ull a, ull b) {
    asm("fma.rn.f32x2 %0, %1, %2, %0;" : "+l"(d) : "l"(a), "l"(b));
}
__device__ __forceinline__ ull dup2(float w) {
    ull r; unsigned u = __float_as_uint(w);
    asm("mov.b64 %0, {%1, %1};" : "=l"(r) : "r"(u)); return r;
}
__device__ __forceinline__ float2 unp2(ull v) {
    unsigned lo, hi;
    asm("mov.b64 {%0, %1}, %2;" : "=r"(lo), "=r"(hi) : "l"(v));
    return make_float2(__uint_as_float(lo), __uint_as_float(hi));
}
__device__ __forceinline__ unsigned cvt_tf32(float f) {
    unsigned u;
    asm("cvt.rna.tf32.f32 %0, %1;" : "=r"(u) : "f"(f));
    return u;
}

// ---------------- K0: zero agg + stats ----------------
__global__ __launch_bounds__(256) void k_zero(int n4) {
    int t = blockIdx.x * 256 + threadIdx.x;
    float4 z = make_float4(0.f, 0.f, 0.f, 0.f);
    if (t < n4) reinterpret_cast<float4*>(g_agg)[t] = z;
    if (t < 384) g_stats[t] = 0.f;
}

// ---------------- K1 (frozen): h_raw = ReLU(nodes @ W_in + b), h stats ------------
__global__ __launch_bounds__(256) void k1_input(
    const float* __restrict__ nodes, const float* __restrict__ W,
    const float* __restrict__ b, int Nn)
{
    __shared__ float sWt[32 * 64];
    __shared__ ulonglong2 sX[32 * 17];
    __shared__ float rs[64], rq[64];
    int tid = threadIdx.x;
    for (int i = tid; i < 2048; i += 256) sWt[i] = W[i];
    if (tid < 64) { rs[tid] = 0.f; rq[tid] = 0.f; }
    int c = tid & 31, wp = tid >> 5;
    ull bl = dup2(b[c]), bh = dup2(b[c + 32]);
    float s0 = 0.f, q0 = 0.f, s1 = 0.f, q1 = 0.f;
    float* sXf = (float*)sX;

    for (int tile = blockIdx.x * 64; tile < Nn; tile += gridDim.x * 64) {
        __syncthreads();
        int cnt = Nn - tile; if (cnt > 64) cnt = 64;
        for (int i = tid; i < 64 * 32; i += 256) {
            int n = i >> 5, k = i & 31;
            float v = (n < cnt) ? nodes[(size_t)(tile + n) * 32 + k] : 0.f;
            sXf[(n >> 1) * 68 + k * 2 + (n & 1)] = v;
        }
        __syncthreads();

        ull a0[4], a1[4];
        #pragma unroll
        for (int p = 0; p < 4; p++) { a0[p] = bl; a1[p] = bh; }
        #pragma unroll
        for (int k2 = 0; k2 < 16; k2++) {
            int k = k2 * 2;
            ull w0 = dup2(sWt[k * 64 + c]);
            ull w1 = dup2(sWt[k * 64 + c + 32]);
            ull w2 = dup2(sWt[k * 64 + 64 + c]);
            ull w3 = dup2(sWt[k * 64 + 64 + c + 32]);
            #pragma unroll
            for (int p = 0; p < 4; p++) {
                ulonglong2 x = sX[(wp * 4 + p) * 17 + k2];
                ffma2(a0[p], x.x, w0); ffma2(a1[p], x.x, w1);
                ffma2(a0[p], x.y, w2); ffma2(a1[p], x.y, w3);
            }
        }
        #pragma unroll
        for (int p = 0; p < 4; p++) {
            float2 f0 = unp2(a0[p]), f1 = unp2(a1[p]);
            int n0 = tile + wp * 8 + 2 * p;
            float v;
            if (n0 < Nn) {
                v = fmaxf(f0.x, 0.f); g_buf_h[(size_t)n0 * 64 + c] = v;        s0 += v; q0 += v * v;
                v = fmaxf(f1.x, 0.f); g_buf_h[(size_t)n0 * 64 + c + 32] = v;   s1 += v; q1 += v * v;
            }
            if (n0 + 1 < Nn) {
                v = fmaxf(f0.y, 0.f); g_buf_h[(size_t)(n0 + 1) * 64 + c] = v;      s0 += v; q0 += v * v;
                v = fmaxf(f1.y, 0.f); g_buf_h[(size_t)(n0 + 1) * 64 + c + 32] = v; s1 += v; q1 += v * v;
            }
        }
    }
    __syncthreads();
    atomicAdd(&rs[c], s0);      atomicAdd(&rq[c], q0);
    atomicAdd(&rs[c + 32], s1); atomicAdd(&rq[c + 32], q1);
    __syncthreads();
    if (tid < 64) { atomicAdd(&g_stats[tid], rs[tid]); atomicAdd(&g_stats[64 + tid], rq[tid]); }
}

// ---------------- K2 (frozen): m_raw = ReLU(BN(h) @ W_msg + b), BN folded ---------
__global__ __launch_bounds__(256) void k2_msg(
    const float* __restrict__ Wm, const float* __restrict__ bm,
    const float* __restrict__ gam, const float* __restrict__ bet,
    int Nn, float invN)
{
    __shared__ float sWt[64 * 32];
    __shared__ ulonglong2 sH[32 * 33];
    __shared__ float sSc[64], sSh[64], sB[32];
    __shared__ float rs[32], rq[32];
    int tid = threadIdx.x;
    if (tid < 64) {
        float mean = g_stats[tid] * invN;
        float var  = fmaf(-mean, mean, g_stats[64 + tid] * invN);
        float r = rsqrtf(var + EPS);
        float s = gam[tid] * r;
        sSc[tid] = s; sSh[tid] = bet[tid] - mean * s;
    }
    if (tid < 32) { sB[tid] = bm[tid]; rs[tid] = 0.f; rq[tid] = 0.f; }
    __syncthreads();
    for (int i = tid; i < 2048; i += 256) sWt[i] = Wm[i] * sSc[i >> 5];
    {
        int cc = tid & 31, part = tid >> 5;
        float acc = 0.f;
        #pragma unroll
        for (int j = part * 8; j < part * 8 + 8; j++) acc += sSh[j] * Wm[j * 32 + cc];
        atomicAdd(&sB[cc], acc);
    }
    __syncthreads();
    int c = tid & 31, wp = tid >> 5;
    ull bl = dup2(sB[c]);
    float s0 = 0.f, q0 = 0.f;
    float* sHf = (float*)sH;

    for (int tile = blockIdx.x * 64; tile < Nn; tile += gridDim.x * 64) {
        __syncthreads();
        int cnt = Nn - tile; if (cnt > 64) cnt = 64;
        for (int i = tid; i < 64 * 64; i += 256) {
            int n = i >> 6, k = i & 63;
            float v = (n < cnt) ? g_buf_h[(size_t)(tile + n) * 64 + k] : 0.f;
            sHf[(n >> 1) * 132 + k * 2 + (n & 1)] = v;
        }
        __syncthreads();

        ull a[4];
        #pragma unroll
        for (int p = 0; p < 4; p++) a[p] = bl;
        #pragma unroll 8
        for (int k2 = 0; k2 < 32; k2++) {
            int k = k2 * 2;
            ull w0 = dup2(sWt[k * 32 + c]);
            ull w1 = dup2(sWt[k * 32 + 32 + c]);
            #pragma unroll
            for (int p = 0; p < 4; p++) {
                ulonglong2 x = sH[(wp * 4 + p) * 33 + k2];
                ffma2(a[p], x.x, w0); ffma2(a[p], x.y, w1);
            }
        }
        #pragma unroll
        for (int p = 0; p < 4; p++) {
            float2 f = unp2(a[p]);
            int n0 = tile + wp * 8 + 2 * p;
            if (n0 < Nn)     { float v = fmaxf(f.x, 0.f); g_buf_m[(size_t)n0 * 32 + c] = v;       s0 += v; q0 += v * v; }
            if (n0 + 1 < Nn) { float v = fmaxf(f.y, 0.f); g_buf_m[(size_t)(n0 + 1) * 32 + c] = v; s0 += v; q0 += v * v; }
        }
    }
    __syncthreads();
    atomicAdd(&rs[c], s0); atomicAdd(&rq[c], q0);
    __syncthreads();
    if (tid < 32) { atomicAdd(&g_stats[128 + tid], rs[tid]); atomicAdd(&g_stats[192 + tid], rq[tid]); }
}

// ---------------- K3 (frozen, ILP 8, at LTS ceiling): 8 edges / group --------------
__global__ __launch_bounds__(256) void k3_edges(
    const int* __restrict__ esrc, const int* __restrict__ edst,
    const float* __restrict__ gam, const float* __restrict__ bet,
    int E, float invN)
{
    __shared__ float sc[32], sh[32];
    if (threadIdx.x < 32) {
        int c = threadIdx.x;
        float mean = g_stats[128 + c] * invN;
        float var  = fmaf(-mean, mean, g_stats[192 + c] * invN);
        float r = rsqrtf(var + EPS);
        float s = gam[c] * r;
        sc[c] = s; sh[c] = bet[c] - mean * s;
    }
    __syncthreads();
    long long t = (long long)blockIdx.x * 256 + threadIdx.x;
    int g = (int)(t >> 3);
    int e0 = g * 8;
    if (e0 >= E) return;
    int j = (int)(t & 7);
    int c0 = j * 4;
    float scx = sc[c0], scy = sc[c0 + 1], scz = sc[c0 + 2], scw = sc[c0 + 3];
    float shx = sh[c0], shy = sh[c0 + 1], shz = sh[c0 + 2], shw = sh[c0 + 3];
    const float4* mp = (const float4*)g_buf_m;

    if (e0 + 8 <= E) {
        int4 sA = *(const int4*)(esrc + e0);
        int4 sB4 = *(const int4*)(esrc + e0 + 4);
        int4 dA = *(const int4*)(edst + e0);
        int4 dB = *(const int4*)(edst + e0 + 4);
        int ss[8] = {sA.x, sA.y, sA.z, sA.w, sB4.x, sB4.y, sB4.z, sB4.w};
        int dd[8] = {dA.x, dA.y, dA.z, dA.w, dB.x, dB.y, dB.z, dB.w};
        float4 v[8];
        #pragma unroll
        for (int i = 0; i < 8; i++) v[i] = __ldg(mp + (size_t)ss[i] * 8 + j);
        #pragma unroll
        for (int i = 0; i < 8; i++) {
            float x = fmaf(v[i].x, scx, shx), y = fmaf(v[i].y, scy, shy);
            float z = fmaf(v[i].z, scz, shz), w = fmaf(v[i].w, scw, shw);
            float* p = g_agg + (size_t)dd[i] * 32 + c0;
            asm volatile("red.global.add.v4.f32 [%0], {%1,%2,%3,%4};"
                         :: "l"(p), "f"(x), "f"(y), "f"(z), "f"(w) : "memory");
        }
    } else {
        for (int e = e0; e < E; e++) {
            int s = esrc[e], d = edst[e];
            float4 v = __ldg(mp + (size_t)s * 8 + j);
            float x = fmaf(v.x, scx, shx), y = fmaf(v.y, scy, shy);
            float z = fmaf(v.z, scz, shz), w = fmaf(v.w, scw, shw);
            float* p = g_agg + (size_t)d * 32 + c0;
            asm volatile("red.global.add.v4.f32 [%0], {%1,%2,%3,%4};"
                         :: "l"(p), "f"(x), "f"(y), "f"(z), "f"(w) : "memory");
        }
    }
}

// ---------------- K4 v3 (tf32 mma.sync): u_raw = ReLU([agg,BN(h),goal]@W + b) ------
// Tile 64 nodes x 64 ch; warp = m-strip (wp&3)*16 nodes x n-half (wp>>2)*32 ch.
// m16n8k8 tf32 fragments; A from sX (stride 116: banks 20g+t, conflict-free);
// B from sWt (stride 72: banks 8t+g, conflict-free). Bias pre-loaded into accum.
__global__ __launch_bounds__(256) void k4_update(
    const float* __restrict__ goal, const float* __restrict__ Wu,
    const float* __restrict__ bu, const float* __restrict__ gam,
    const float* __restrict__ bet, int Nn, float invN)
{
    __shared__ __align__(16) float sWt[112 * 72];   // 31.5 KB tf32 bits [k][c]
    __shared__ __align__(16) float sX [64 * 116];   // 29.0 KB tf32 bits [node][k]
    __shared__ float sSc[64], sSh[64], sB[64];
    __shared__ float rs[64], rq[64];
    int tid = threadIdx.x;
    if (tid < 64) {
        float mean = g_stats[tid] * invN;
        float var  = fmaf(-mean, mean, g_stats[64 + tid] * invN);
        float r = rsqrtf(var + EPS);
        float s = gam[tid] * r;
        sSc[tid] = s; sSh[tid] = bet[tid] - mean * s;
        sB[tid] = bu[tid]; rs[tid] = 0.f; rq[tid] = 0.f;
    }
    __syncthreads();
    for (int i = tid; i < 112 * 64; i += 256) {
        int k = i >> 6, cc = i & 63;
        float f = (k >= 32 && k < 96) ? sSc[k - 32] : 1.f;
        sWt[k * 72 + cc] = __uint_as_float(cvt_tf32(Wu[i] * f));
    }
    {
        int cc = tid & 63, part = tid >> 6;
        float acc = 0.f;
        #pragma unroll
        for (int j = part * 16; j < part * 16 + 16; j++) acc += sSh[j] * Wu[(32 + j) * 64 + cc];
        atomicAdd(&sB[cc], acc);
    }
    __syncthreads();

    int lane = tid & 31, wp = tid >> 5;
    int g = lane >> 2, t = lane & 3;
    int mb = (wp & 3) * 16;       // m-strip base node (in tile)
    int nb = (wp >> 2) * 32;      // n-half base channel
    float s_[4][2], q_[4][2];
    #pragma unroll
    for (int n = 0; n < 4; n++) { s_[n][0] = s_[n][1] = q_[n][0] = q_[n][1] = 0.f; }
    const float4* ap = (const float4*)g_agg;
    const float4* hp = (const float4*)g_buf_h;
    const float4* gp = (const float4*)goal;
    float4 z4 = make_float4(0.f, 0.f, 0.f, 0.f);
    const unsigned* sXu = (const unsigned*)sX;
    const unsigned* sWu = (const unsigned*)sWt;

    for (int tile = blockIdx.x * 64; tile < Nn; tile += gridDim.x * 64) {
        __syncthreads();
        #pragma unroll
        for (int it = 0; it < 7; it++) {
            int f = tid + it * 256;            // 0..1791; node row = 28 float4
            int n = f / 28, r = f - n * 28;
            int gn = tile + n;
            float4 v = z4;
            if (gn < Nn) {
                v = (r < 8)  ? ap[(size_t)gn * 8 + r]
                  : (r < 24) ? hp[(size_t)gn * 16 + (r - 8)]
                             : gp[(size_t)gn * 4 + (r - 24)];
            }
            float4 o;
            o.x = __uint_as_float(cvt_tf32(v.x));
            o.y = __uint_as_float(cvt_tf32(v.y));
            o.z = __uint_as_float(cvt_tf32(v.z));
            o.w = __uint_as_float(cvt_tf32(v.w));
            *reinterpret_cast<float4*>(&sX[n * 116 + r * 4]) = o;
        }
        __syncthreads();

        float c0[4], c1[4], c2[4], c3[4];
        #pragma unroll
        for (int n = 0; n < 4; n++) {
            int ch = nb + 8 * n + 2 * t;
            c0[n] = sB[ch]; c1[n] = sB[ch + 1];
            c2[n] = c0[n];  c3[n] = c1[n];
        }
        #pragma unroll
        for (int ks = 0; ks < 14; ks++) {
            int k0 = ks * 8;
            unsigned a0 = sXu[(mb + g)     * 116 + k0 + t];
            unsigned a1 = sXu[(mb + g + 8) * 116 + k0 + t];
            unsigned a2 = sXu[(mb + g)     * 116 + k0 + t + 4];
            unsigned a3 = sXu[(mb + g + 8) * 116 + k0 + t + 4];
            #pragma unroll
            for (int n = 0; n < 4; n++) {
                int ncol = nb + 8 * n + g;
                unsigned b0 = sWu[(k0 + t)     * 72 + ncol];
                unsigned b1 = sWu[(k0 + t + 4) * 72 + ncol];
                asm volatile(
                    "mma.sync.aligned.m16n8k8.row.col.f32.tf32.tf32.f32 "
                    "{%0,%1,%2,%3}, {%4,%5,%6,%7}, {%8,%9}, {%0,%1,%2,%3};"
                    : "+f"(c0[n]), "+f"(c1[n]), "+f"(c2[n]), "+f"(c3[n])
                    : "r"(a0), "r"(a1), "r"(a2), "r"(a3), "r"(b0), "r"(b1));
            }
        }
        int gn0 = tile + mb + g, gn1 = gn0 + 8;
        #pragma unroll
        for (int n = 0; n < 4; n++) {
            int ch = nb + 8 * n + 2 * t;
            if (gn0 < Nn) {
                float v0 = fmaxf(c0[n], 0.f), v1 = fmaxf(c1[n], 0.f);
                *reinterpret_cast<float2*>(&g_buf_u[(size_t)gn0 * 64 + ch]) = make_float2(v0, v1);
                s_[n][0] += v0; q_[n][0] += v0 * v0;
                s_[n][1] += v1; q_[n][1] += v1 * v1;
            }
            if (gn1 < Nn) {
                float v0 = fmaxf(c2[n], 0.f), v1 = fmaxf(c3[n], 0.f);
                *reinterpret_cast<float2*>(&g_buf_u[(size_t)gn1 * 64 + ch]) = make_float2(v0, v1);
                s_[n][0] += v0; q_[n][0] += v0 * v0;
                s_[n][1] += v1; q_[n][1] += v1 * v1;
            }
        }
    }
    __syncthreads();
    #pragma unroll
    for (int n = 0; n < 4; n++) {
        int ch = nb + 8 * n + 2 * t;
        atomicAdd(&rs[ch], s_[n][0]);     atomicAdd(&rq[ch], q_[n][0]);
        atomicAdd(&rs[ch + 1], s_[n][1]); atomicAdd(&rq[ch + 1], q_[n][1]);
    }
    __syncthreads();
    if (tid < 64) { atomicAdd(&g_stats[256 + tid], rs[tid]); atomicAdd(&g_stats[320 + tid], rq[tid]); }
}

// ---------------- K5 (frozen, vectorized + stride-68 weights) ----------------------
__global__ __launch_bounds__(256) void k5_output(
    const float* __restrict__ Wo, const float* __restrict__ bo,
    const float* __restrict__ gam, const float* __restrict__ bet,
    float* __restrict__ out_u, float* __restrict__ out_o,
    int Nn, float invN)
{
    __shared__ __align__(16) float sWt[8 * 68];   // transposed [oc][k], stride 68
    __shared__ __align__(16) float sU[4 * 68];
    __shared__ float sScale[64], sShift[64];
    int tid = threadIdx.x;
    for (int i = tid; i < 512; i += 256) {
        int k = i >> 3, oc = i & 7;
        sWt[oc * 68 + k] = Wo[i];
    }
    if (tid < 64) {
        float mean = g_stats[256 + tid] * invN;
        float var  = fmaf(-mean, mean, g_stats[320 + tid] * invN);
        float r    = rsqrtf(var + EPS);
        float sc   = gam[tid] * r;
        sScale[tid] = sc; sShift[tid] = bet[tid] - mean * sc;
    }
    int c = tid & 63, l = tid >> 6;

    for (int base = blockIdx.x * 4; base < Nn; base += gridDim.x * 4) {
        __syncthreads();
        int n = base + l;
        float u = 0.f;
        if (n < Nn) {
            u = fmaf(g_buf_u[(size_t)n * 64 + c], sScale[c], sShift[c]);
            out_u[(size_t)n * 64 + c] = u;
        }
        sU[l * 68 + c] = u;
        __syncthreads();
        if (tid < 32) {
            int ln = tid >> 3, oc = tid & 7;
            int nn = base + ln;
            if (nn < Nn) {
                float acc = bo[oc];
                #pragma unroll
                for (int kk = 0; kk < 16; kk++) {
                    float4 uv = *reinterpret_cast<const float4*>(&sU[ln * 68 + kk * 4]);
                    float4 wv = *reinterpret_cast<const float4*>(&sWt[oc * 68 + kk * 4]);
                    acc = fmaf(uv.x, wv.x, acc); acc = fmaf(uv.y, wv.y, acc);
                    acc = fmaf(uv.z, wv.z, acc); acc = fmaf(uv.w, wv.w, acc);
                }
                out_o[(size_t)nn * 8 + oc] = acc;
            }
        }
    }
}

// ---------------- host launcher ----------------
extern "C" void kernel_launch(void* const* d_in, const int* in_sizes, int n_in,
                              void* d_out, int out_size)
{
    const float* nodes  = (const float*)d_in[0];
    const float* goal   = (const float*)d_in[1];
    const int*   esrc   = (const int*)d_in[2];
    const int*   edst   = (const int*)d_in[3];
    const float* W_in   = (const float*)d_in[6];
    const float* b_in   = (const float*)d_in[7];
    const float* g_in   = (const float*)d_in[8];
    const float* be_in  = (const float*)d_in[9];
    const float* W_msg  = (const float*)d_in[10];
    const float* b_msg  = (const float*)d_in[11];
    const float* g_msg  = (const float*)d_in[12];
    const float* be_msg = (const float*)d_in[13];
    const float* W_upd  = (const float*)d_in[14];
    const float* b_upd  = (const float*)d_in[15];
    const float* g_upd  = (const float*)d_in[16];
    const float* be_upd = (const float*)d_in[17];
    const float* W_out  = (const float*)d_in[18];
    const float* b_out  = (const float*)d_in[19];

    int N = in_sizes[0] / 32;
    int E = in_sizes[2];
    float invN = 1.0f / (float)N;

    float* dout = (float*)d_out;
    float* out_u;
    float* out_o;
    if ((long long)out_size >= (long long)N * 72) {        // tuple (u, out) concatenated
        out_u = dout;
        out_o = dout + (size_t)N * 64;
    } else if ((long long)out_size == (long long)N * 8) {  // only `out`
        void* p; cudaGetSymbolAddress(&p, g_buf_h);
        out_u = (float*)p;  out_o = dout;
    } else {                                               // only `u`
        void* p; cudaGetSymbolAddress(&p, g_buf_h);
        out_u = dout;       out_o = (float*)p;
    }

    int n4 = N * 8;   // N*32/4 float4s of agg
    k_zero  <<<(n4 + 255) / 256, 256>>>(n4);
    k1_input<<<592, 256>>>(nodes, W_in, b_in, N);
    k2_msg  <<<592, 256>>>(W_msg, b_msg, g_in, be_in, N, invN);
    long long groups = ((long long)E + 7) / 8;
    long long thr = groups * 8;
    k3_edges<<<(int)((thr + 255) / 256), 256>>>(esrc, edst, g_msg, be_msg, E, invN);
    k4_update<<<444, 256>>>(goal, W_upd, b_upd, g_in, be_in, N, invN);
    k5_output<<<2960, 256>>>(W_out, b_out, g_upd, be_upd, out_u, out_o, N, invN);
}

// round 16
// speedup vs baseline: 1.3483x; 1.0240x over previous
#include <cuda_runtime.h>

#define NMAX 100000
#define EPS 1e-5f

typedef unsigned long long ull;

// ---------------- scratch ----------------
__device__ float g_buf_h[(size_t)NMAX * 64];   // h_raw (ReLU output, pre-BN)
__device__ float g_buf_m[(size_t)NMAX * 32];   // m_raw (pre-BN)
__device__ float g_agg  [(size_t)NMAX * 32];   // segment-sum of BN(m)
__device__ float g_buf_u[(size_t)NMAX * 64];   // u_raw
// [0:64) sum_h [64:128) sq_h [128:160) sum_m [192:224) sq_m [256:320) sum_u [320:384) sq_u
__device__ float g_stats[384];

// ---------------- f32x2 helpers ----------------
__device__ __forceinline__ void ffma2(ull &d, ull a, ull b) {
    asm("fma.rn.f32x2 %0, %1, %2, %0;" : "+l"(d) : "l"(a), "l"(b));
}
__device__ __forceinline__ ull dup2(float w) {
    ull r; unsigned u = __float_as_uint(w);
    asm("mov.b64 %0, {%1, %1};" : "=l"(r) : "r"(u)); return r;
}
__device__ __forceinline__ float2 unp2(ull v) {
    unsigned lo, hi;
    asm("mov.b64 {%0, %1}, %2;" : "=r"(lo), "=r"(hi) : "l"(v));
    return make_float2(__uint_as_float(lo), __uint_as_float(hi));
}
__device__ __forceinline__ unsigned cvt_tf32(float f) {
    unsigned u;
    asm("cvt.rna.tf32.f32 %0, %1;" : "=r"(u) : "f"(f));
    return u;
}

// ---------------- K0: zero agg + stats ----------------
__global__ __launch_bounds__(256) void k_zero(int n4) {
    int t = blockIdx.x * 256 + threadIdx.x;
    float4 z = make_float4(0.f, 0.f, 0.f, 0.f);
    if (t < n4) reinterpret_cast<float4*>(g_agg)[t] = z;
    if (t < 384) g_stats[t] = 0.f;
}

// ---------------- K1 (frozen): h_raw = ReLU(nodes @ W_in + b), h stats ------------
__global__ __launch_bounds__(256) void k1_input(
    const float* __restrict__ nodes, const float* __restrict__ W,
    const float* __restrict__ b, int Nn)
{
    __shared__ float sWt[32 * 64];
    __shared__ ulonglong2 sX[32 * 17];
    __shared__ float rs[64], rq[64];
    int tid = threadIdx.x;
    for (int i = tid; i < 2048; i += 256) sWt[i] = W[i];
    if (tid < 64) { rs[tid] = 0.f; rq[tid] = 0.f; }
    int c = tid & 31, wp = tid >> 5;
    ull bl = dup2(b[c]), bh = dup2(b[c + 32]);
    float s0 = 0.f, q0 = 0.f, s1 = 0.f, q1 = 0.f;
    float* sXf = (float*)sX;

    for (int tile = blockIdx.x * 64; tile < Nn; tile += gridDim.x * 64) {
        __syncthreads();
        int cnt = Nn - tile; if (cnt > 64) cnt = 64;
        for (int i = tid; i < 64 * 32; i += 256) {
            int n = i >> 5, k = i & 31;
            float v = (n < cnt) ? nodes[(size_t)(tile + n) * 32 + k] : 0.f;
            sXf[(n >> 1) * 68 + k * 2 + (n & 1)] = v;
        }
        __syncthreads();

        ull a0[4], a1[4];
        #pragma unroll
        for (int p = 0; p < 4; p++) { a0[p] = bl; a1[p] = bh; }
        #pragma unroll
        for (int k2 = 0; k2 < 16; k2++) {
            int k = k2 * 2;
            ull w0 = dup2(sWt[k * 64 + c]);
            ull w1 = dup2(sWt[k * 64 + c + 32]);
            ull w2 = dup2(sWt[k * 64 + 64 + c]);
            ull w3 = dup2(sWt[k * 64 + 64 + c + 32]);
            #pragma unroll
            for (int p = 0; p < 4; p++) {
                ulonglong2 x = sX[(wp * 4 + p) * 17 + k2];
                ffma2(a0[p], x.x, w0); ffma2(a1[p], x.x, w1);
                ffma2(a0[p], x.y, w2); ffma2(a1[p], x.y, w3);
            }
        }
        #pragma unroll
        for (int p = 0; p < 4; p++) {
            float2 f0 = unp2(a0[p]), f1 = unp2(a1[p]);
            int n0 = tile + wp * 8 + 2 * p;
            float v;
            if (n0 < Nn) {
                v = fmaxf(f0.x, 0.f); g_buf_h[(size_t)n0 * 64 + c] = v;        s0 += v; q0 += v * v;
                v = fmaxf(f1.x, 0.f); g_buf_h[(size_t)n0 * 64 + c + 32] = v;   s1 += v; q1 += v * v;
            }
            if (n0 + 1 < Nn) {
                v = fmaxf(f0.y, 0.f); g_buf_h[(size_t)(n0 + 1) * 64 + c] = v;      s0 += v; q0 += v * v;
                v = fmaxf(f1.y, 0.f); g_buf_h[(size_t)(n0 + 1) * 64 + c + 32] = v; s1 += v; q1 += v * v;
            }
        }
    }
    __syncthreads();
    atomicAdd(&rs[c], s0);      atomicAdd(&rq[c], q0);
    atomicAdd(&rs[c + 32], s1); atomicAdd(&rq[c + 32], q1);
    __syncthreads();
    if (tid < 64) { atomicAdd(&g_stats[tid], rs[tid]); atomicAdd(&g_stats[64 + tid], rq[tid]); }
}

// ---------------- K2 v2 (tf32 mma, same verified fragment layout as k4) ------------
// m_raw = ReLU(BN(h) @ W_msg + b), BN folded into tf32 weights.
// Tile 64 nodes x 32 ch; warp = (wp&3)*16 nodes x (wp>>2)*16 ch; 8 k-steps.
// A: sX stride 68 (banks 4g+t, conflict-free). B: sWt stride 40 (banks 8t+g, c-free).
__global__ __launch_bounds__(256) void k2_msg(
    const float* __restrict__ Wm, const float* __restrict__ bm,
    const float* __restrict__ gam, const float* __restrict__ bet,
    int Nn, float invN)
{
    __shared__ __align__(16) float sWt[64 * 40];   // 10 KB tf32 bits [k][c]
    __shared__ __align__(16) float sX [64 * 68];   // 17 KB tf32 bits [node][k]
    __shared__ float sSc[64], sSh[64], sB[32];
    __shared__ float rs[32], rq[32];
    int tid = threadIdx.x;
    if (tid < 64) {
        float mean = g_stats[tid] * invN;
        float var  = fmaf(-mean, mean, g_stats[64 + tid] * invN);
        float r = rsqrtf(var + EPS);
        float s = gam[tid] * r;
        sSc[tid] = s; sSh[tid] = bet[tid] - mean * s;
    }
    if (tid < 32) { sB[tid] = bm[tid]; rs[tid] = 0.f; rq[tid] = 0.f; }
    __syncthreads();
    for (int i = tid; i < 2048; i += 256) {
        int k = i >> 5, cc = i & 31;
        sWt[k * 40 + cc] = __uint_as_float(cvt_tf32(Wm[i] * sSc[k]));
    }
    {
        int cc = tid & 31, part = tid >> 5;
        float acc = 0.f;
        #pragma unroll
        for (int j = part * 8; j < part * 8 + 8; j++) acc += sSh[j] * Wm[j * 32 + cc];
        atomicAdd(&sB[cc], acc);
    }
    __syncthreads();

    int lane = tid & 31, wp = tid >> 5;
    int g = lane >> 2, t = lane & 3;
    int mb = (wp & 3) * 16;       // m-strip base node
    int nb = (wp >> 2) * 16;      // n-half base channel (0 or 16)
    float s_[2][2], q_[2][2];
    #pragma unroll
    for (int n = 0; n < 2; n++) { s_[n][0] = s_[n][1] = q_[n][0] = q_[n][1] = 0.f; }
    const float4* hp = (const float4*)g_buf_h;
    float4 z4 = make_float4(0.f, 0.f, 0.f, 0.f);
    const unsigned* sXu = (const unsigned*)sX;
    const unsigned* sWu = (const unsigned*)sWt;

    for (int tile = blockIdx.x * 64; tile < Nn; tile += gridDim.x * 64) {
        __syncthreads();
        #pragma unroll
        for (int it = 0; it < 4; it++) {
            int f = tid + it * 256;            // 0..1023; node row = 16 float4
            int n = f >> 4, r = f & 15;
            int gn = tile + n;
            float4 v = (gn < Nn) ? hp[(size_t)gn * 16 + r] : z4;
            float4 o;
            o.x = __uint_as_float(cvt_tf32(v.x));
            o.y = __uint_as_float(cvt_tf32(v.y));
            o.z = __uint_as_float(cvt_tf32(v.z));
            o.w = __uint_as_float(cvt_tf32(v.w));
            *reinterpret_cast<float4*>(&sX[n * 68 + r * 4]) = o;
        }
        __syncthreads();

        float c0[2], c1[2], c2[2], c3[2];
        #pragma unroll
        for (int n = 0; n < 2; n++) {
            int ch = nb + 8 * n + 2 * t;
            c0[n] = sB[ch]; c1[n] = sB[ch + 1];
            c2[n] = c0[n];  c3[n] = c1[n];
        }
        #pragma unroll
        for (int ks = 0; ks < 8; ks++) {
            int k0 = ks * 8;
            unsigned a0 = sXu[(mb + g)     * 68 + k0 + t];
            unsigned a1 = sXu[(mb + g + 8) * 68 + k0 + t];
            unsigned a2 = sXu[(mb + g)     * 68 + k0 + t + 4];
            unsigned a3 = sXu[(mb + g + 8) * 68 + k0 + t + 4];
            #pragma unroll
            for (int n = 0; n < 2; n++) {
                int ncol = nb + 8 * n + g;
                unsigned b0 = sWu[(k0 + t)     * 40 + ncol];
                unsigned b1 = sWu[(k0 + t + 4) * 40 + ncol];
                asm volatile(
                    "mma.sync.aligned.m16n8k8.row.col.f32.tf32.tf32.f32 "
                    "{%0,%1,%2,%3}, {%4,%5,%6,%7}, {%8,%9}, {%0,%1,%2,%3};"
                    : "+f"(c0[n]), "+f"(c1[n]), "+f"(c2[n]), "+f"(c3[n])
                    : "r"(a0), "r"(a1), "r"(a2), "r"(a3), "r"(b0), "r"(b1));
            }
        }
        int gn0 = tile + mb + g, gn1 = gn0 + 8;
        #pragma unroll
        for (int n = 0; n < 2; n++) {
            int ch = nb + 8 * n + 2 * t;
            if (gn0 < Nn) {
                float v0 = fmaxf(c0[n], 0.f), v1 = fmaxf(c1[n], 0.f);
                *reinterpret_cast<float2*>(&g_buf_m[(size_t)gn0 * 32 + ch]) = make_float2(v0, v1);
                s_[n][0] += v0; q_[n][0] += v0 * v0;
                s_[n][1] += v1; q_[n][1] += v1 * v1;
            }
            if (gn1 < Nn) {
                float v0 = fmaxf(c2[n], 0.f), v1 = fmaxf(c3[n], 0.f);
                *reinterpret_cast<float2*>(&g_buf_m[(size_t)gn1 * 32 + ch]) = make_float2(v0, v1);
                s_[n][0] += v0; q_[n][0] += v0 * v0;
                s_[n][1] += v1; q_[n][1] += v1 * v1;
            }
        }
    }
    __syncthreads();
    #pragma unroll
    for (int n = 0; n < 2; n++) {
        int ch = nb + 8 * n + 2 * t;
        atomicAdd(&rs[ch], s_[n][0]);     atomicAdd(&rq[ch], q_[n][0]);
        atomicAdd(&rs[ch + 1], s_[n][1]); atomicAdd(&rq[ch + 1], q_[n][1]);
    }
    __syncthreads();
    if (tid < 32) { atomicAdd(&g_stats[128 + tid], rs[tid]); atomicAdd(&g_stats[192 + tid], rq[tid]); }
}

// ---------------- K3 (frozen, ILP 8, at LTS ceiling): 8 edges / group --------------
__global__ __launch_bounds__(256) void k3_edges(
    const int* __restrict__ esrc, const int* __restrict__ edst,
    const float* __restrict__ gam, const float* __restrict__ bet,
    int E, float invN)
{
    __shared__ float sc[32], sh[32];
    if (threadIdx.x < 32) {
        int c = threadIdx.x;
        float mean = g_stats[128 + c] * invN;
        float var  = fmaf(-mean, mean, g_stats[192 + c] * invN);
        float r = rsqrtf(var + EPS);
        float s = gam[c] * r;
        sc[c] = s; sh[c] = bet[c] - mean * s;
    }
    __syncthreads();
    long long t = (long long)blockIdx.x * 256 + threadIdx.x;
    int g = (int)(t >> 3);
    int e0 = g * 8;
    if (e0 >= E) return;
    int j = (int)(t & 7);
    int c0 = j * 4;
    float scx = sc[c0], scy = sc[c0 + 1], scz = sc[c0 + 2], scw = sc[c0 + 3];
    float shx = sh[c0], shy = sh[c0 + 1], shz = sh[c0 + 2], shw = sh[c0 + 3];
    const float4* mp = (const float4*)g_buf_m;

    if (e0 + 8 <= E) {
        int4 sA = *(const int4*)(esrc + e0);
        int4 sB4 = *(const int4*)(esrc + e0 + 4);
        int4 dA = *(const int4*)(edst + e0);
        int4 dB = *(const int4*)(edst + e0 + 4);
        int ss[8] = {sA.x, sA.y, sA.z, sA.w, sB4.x, sB4.y, sB4.z, sB4.w};
        int dd[8] = {dA.x, dA.y, dA.z, dA.w, dB.x, dB.y, dB.z, dB.w};
        float4 v[8];
        #pragma unroll
        for (int i = 0; i < 8; i++) v[i] = __ldg(mp + (size_t)ss[i] * 8 + j);
        #pragma unroll
        for (int i = 0; i < 8; i++) {
            float x = fmaf(v[i].x, scx, shx), y = fmaf(v[i].y, scy, shy);
            float z = fmaf(v[i].z, scz, shz), w = fmaf(v[i].w, scw, shw);
            float* p = g_agg + (size_t)dd[i] * 32 + c0;
            asm volatile("red.global.add.v4.f32 [%0], {%1,%2,%3,%4};"
                         :: "l"(p), "f"(x), "f"(y), "f"(z), "f"(w) : "memory");
        }
    } else {
        for (int e = e0; e < E; e++) {
            int s = esrc[e], d = edst[e];
            float4 v = __ldg(mp + (size_t)s * 8 + j);
            float x = fmaf(v.x, scx, shx), y = fmaf(v.y, scy, shy);
            float z = fmaf(v.z, scz, shz), w = fmaf(v.w, scw, shw);
            float* p = g_agg + (size_t)d * 32 + c0;
            asm volatile("red.global.add.v4.f32 [%0], {%1,%2,%3,%4};"
                         :: "l"(p), "f"(x), "f"(y), "f"(z), "f"(w) : "memory");
        }
    }
}

// ---------------- K4 (frozen WIN, tf32 mma): u_raw = ReLU([agg,BN(h),goal]@W + b) --
__global__ __launch_bounds__(256) void k4_update(
    const float* __restrict__ goal, const float* __restrict__ Wu,
    const float* __restrict__ bu, const float* __restrict__ gam,
    const float* __restrict__ bet, int Nn, float invN)
{
    __shared__ __align__(16) float sWt[112 * 72];   // 31.5 KB tf32 bits [k][c]
    __shared__ __align__(16) float sX [64 * 116];   // 29.0 KB tf32 bits [node][k]
    __shared__ float sSc[64], sSh[64], sB[64];
    __shared__ float rs[64], rq[64];
    int tid = threadIdx.x;
    if (tid < 64) {
        float mean = g_stats[tid] * invN;
        float var  = fmaf(-mean, mean, g_stats[64 + tid] * invN);
        float r = rsqrtf(var + EPS);
        float s = gam[tid] * r;
        sSc[tid] = s; sSh[tid] = bet[tid] - mean * s;
        sB[tid] = bu[tid]; rs[tid] = 0.f; rq[tid] = 0.f;
    }
    __syncthreads();
    for (int i = tid; i < 112 * 64; i += 256) {
        int k = i >> 6, cc = i & 63;
        float f = (k >= 32 && k < 96) ? sSc[k - 32] : 1.f;
        sWt[k * 72 + cc] = __uint_as_float(cvt_tf32(Wu[i] * f));
    }
    {
        int cc = tid & 63, part = tid >> 6;
        float acc = 0.f;
        #pragma unroll
        for (int j = part * 16; j < part * 16 + 16; j++) acc += sSh[j] * Wu[(32 + j) * 64 + cc];
        atomicAdd(&sB[cc], acc);
    }
    __syncthreads();

    int lane = tid & 31, wp = tid >> 5;
    int g = lane >> 2, t = lane & 3;
    int mb = (wp & 3) * 16;       // m-strip base node (in tile)
    int nb = (wp >> 2) * 32;      // n-half base channel
    float s_[4][2], q_[4][2];
    #pragma unroll
    for (int n = 0; n < 4; n++) { s_[n][0] = s_[n][1] = q_[n][0] = q_[n][1] = 0.f; }
    const float4* ap = (const float4*)g_agg;
    const float4* hp = (const float4*)g_buf_h;
    const float4* gp = (const float4*)goal;
    float4 z4 = make_float4(0.f, 0.f, 0.f, 0.f);
    const unsigned* sXu = (const unsigned*)sX;
    const unsigned* sWu = (const unsigned*)sWt;

    for (int tile = blockIdx.x * 64; tile < Nn; tile += gridDim.x * 64) {
        __syncthreads();
        #pragma unroll
        for (int it = 0; it < 7; it++) {
            int f = tid + it * 256;            // 0..1791; node row = 28 float4
            int n = f / 28, r = f - n * 28;
            int gn = tile + n;
            float4 v = z4;
            if (gn < Nn) {
                v = (r < 8)  ? ap[(size_t)gn * 8 + r]
                  : (r < 24) ? hp[(size_t)gn * 16 + (r - 8)]
                             : gp[(size_t)gn * 4 + (r - 24)];
            }
            float4 o;
            o.x = __uint_as_float(cvt_tf32(v.x));
            o.y = __uint_as_float(cvt_tf32(v.y));
            o.z = __uint_as_float(cvt_tf32(v.z));
            o.w = __uint_as_float(cvt_tf32(v.w));
            *reinterpret_cast<float4*>(&sX[n * 116 + r * 4]) = o;
        }
        __syncthreads();

        float c0[4], c1[4], c2[4], c3[4];
        #pragma unroll
        for (int n = 0; n < 4; n++) {
            int ch = nb + 8 * n + 2 * t;
            c0[n] = sB[ch]; c1[n] = sB[ch + 1];
            c2[n] = c0[n];  c3[n] = c1[n];
        }
        #pragma unroll
        for (int ks = 0; ks < 14; ks++) {
            int k0 = ks * 8;
            unsigned a0 = sXu[(mb + g)     * 116 + k0 + t];
            unsigned a1 = sXu[(mb + g + 8) * 116 + k0 + t];
            unsigned a2 = sXu[(mb + g)     * 116 + k0 + t + 4];
            unsigned a3 = sXu[(mb + g + 8) * 116 + k0 + t + 4];
            #pragma unroll
            for (int n = 0; n < 4; n++) {
                int ncol = nb + 8 * n + g;
                unsigned b0 = sWu[(k0 + t)     * 72 + ncol];
                unsigned b1 = sWu[(k0 + t + 4) * 72 + ncol];
                asm volatile(
                    "mma.sync.aligned.m16n8k8.row.col.f32.tf32.tf32.f32 "
                    "{%0,%1,%2,%3}, {%4,%5,%6,%7}, {%8,%9}, {%0,%1,%2,%3};"
                    : "+f"(c0[n]), "+f"(c1[n]), "+f"(c2[n]), "+f"(c3[n])
                    : "r"(a0), "r"(a1), "r"(a2), "r"(a3), "r"(b0), "r"(b1));
            }
        }
        int gn0 = tile + mb + g, gn1 = gn0 + 8;
        #pragma unroll
        for (int n = 0; n < 4; n++) {
            int ch = nb + 8 * n + 2 * t;
            if (gn0 < Nn) {
                float v0 = fmaxf(c0[n], 0.f), v1 = fmaxf(c1[n], 0.f);
                *reinterpret_cast<float2*>(&g_buf_u[(size_t)gn0 * 64 + ch]) = make_float2(v0, v1);
                s_[n][0] += v0; q_[n][0] += v0 * v0;
                s_[n][1] += v1; q_[n][1] += v1 * v1;
            }
            if (gn1 < Nn) {
                float v0 = fmaxf(c2[n], 0.f), v1 = fmaxf(c3[n], 0.f);
                *reinterpret_cast<float2*>(&g_buf_u[(size_t)gn1 * 64 + ch]) = make_float2(v0, v1);
                s_[n][0] += v0; q_[n][0] += v0 * v0;
                s_[n][1] += v1; q_[n][1] += v1 * v1;
            }
        }
    }
    __syncthreads();
    #pragma unroll
    for (int n = 0; n < 4; n++) {
        int ch = nb + 8 * n + 2 * t;
        atomicAdd(&rs[ch], s_[n][0]);     atomicAdd(&rq[ch], q_[n][0]);
        atomicAdd(&rs[ch + 1], s_[n][1]); atomicAdd(&rq[ch + 1], q_[n][1]);
    }
    __syncthreads();
    if (tid < 64) { atomicAdd(&g_stats[256 + tid], rs[tid]); atomicAdd(&g_stats[320 + tid], rq[tid]); }
}

// ---------------- K5 (frozen, vectorized + stride-68 weights) ----------------------
__global__ __launch_bounds__(256) void k5_output(
    const float* __restrict__ Wo, const float* __restrict__ bo,
    const float* __restrict__ gam, const float* __restrict__ bet,
    float* __restrict__ out_u, float* __restrict__ out_o,
    int Nn, float invN)
{
    __shared__ __align__(16) float sWt[8 * 68];   // transposed [oc][k], stride 68
    __shared__ __align__(16) float sU[4 * 68];
    __shared__ float sScale[64], sShift[64];
    int tid = threadIdx.x;
    for (int i = tid; i < 512; i += 256) {
        int k = i >> 3, oc = i & 7;
        sWt[oc * 68 + k] = Wo[i];
    }
    if (tid < 64) {
        float mean = g_stats[256 + tid] * invN;
        float var  = fmaf(-mean, mean, g_stats[320 + tid] * invN);
        float r    = rsqrtf(var + EPS);
        float sc   = gam[tid] * r;
        sScale[tid] = sc; sShift[tid] = bet[tid] - mean * sc;
    }
    int c = tid & 63, l = tid >> 6;

    for (int base = blockIdx.x * 4; base < Nn; base += gridDim.x * 4) {
        __syncthreads();
        int n = base + l;
        float u = 0.f;
        if (n < Nn) {
            u = fmaf(g_buf_u[(size_t)n * 64 + c], sScale[c], sShift[c]);
            out_u[(size_t)n * 64 + c] = u;
        }
        sU[l * 68 + c] = u;
        __syncthreads();
        if (tid < 32) {
            int ln = tid >> 3, oc = tid & 7;
            int nn = base + ln;
            if (nn < Nn) {
                float acc = bo[oc];
                #pragma unroll
                for (int kk = 0; kk < 16; kk++) {
                    float4 uv = *reinterpret_cast<const float4*>(&sU[ln * 68 + kk * 4]);
                    float4 wv = *reinterpret_cast<const float4*>(&sWt[oc * 68 + kk * 4]);
                    acc = fmaf(uv.x, wv.x, acc); acc = fmaf(uv.y, wv.y, acc);
                    acc = fmaf(uv.z, wv.z, acc); acc = fmaf(uv.w, wv.w, acc);
                }
                out_o[(size_t)nn * 8 + oc] = acc;
            }
        }
    }
}

// ---------------- host launcher ----------------
extern "C" void kernel_launch(void* const* d_in, const int* in_sizes, int n_in,
                              void* d_out, int out_size)
{
    const float* nodes  = (const float*)d_in[0];
    const float* goal   = (const float*)d_in[1];
    const int*   esrc   = (const int*)d_in[2];
    const int*   edst   = (const int*)d_in[3];
    const float* W_in   = (const float*)d_in[6];
    const float* b_in   = (const float*)d_in[7];
    const float* g_in   = (const float*)d_in[8];
    const float* be_in  = (const float*)d_in[9];
    const float* W_msg  = (const float*)d_in[10];
    const float* b_msg  = (const float*)d_in[11];
    const float* g_msg  = (const float*)d_in[12];
    const float* be_msg = (const float*)d_in[13];
    const float* W_upd  = (const float*)d_in[14];
    const float* b_upd  = (const float*)d_in[15];
    const float* g_upd  = (const float*)d_in[16];
    const float* be_upd = (const float*)d_in[17];
    const float* W_out  = (const float*)d_in[18];
    const float* b_out  = (const float*)d_in[19];

    int N = in_sizes[0] / 32;
    int E = in_sizes[2];
    float invN = 1.0f / (float)N;

    float* dout = (float*)d_out;
    float* out_u;
    float* out_o;
    if ((long long)out_size >= (long long)N * 72) {        // tuple (u, out) concatenated
        out_u = dout;
        out_o = dout + (size_t)N * 64;
    } else if ((long long)out_size == (long long)N * 8) {  // only `out`
        void* p; cudaGetSymbolAddress(&p, g_buf_h);
        out_u = (float*)p;  out_o = dout;
    } else {                                               // only `u`
        void* p; cudaGetSymbolAddress(&p, g_buf_h);
        out_u = dout;       out_o = (float*)p;
    }

    int n4 = N * 8;   // N*32/4 float4s of agg
    k_zero  <<<(n4 + 255) / 256, 256>>>(n4);
    k1_input<<<592, 256>>>(nodes, W_in, b_in, N);
    k2_msg  <<<592, 256>>>(W_msg, b_msg, g_in, be_in, N, invN);
    long long groups = ((long long)E + 7) / 8;
    long long thr = groups * 8;
    k3_edges<<<(int)((thr + 255) / 256), 256>>>(esrc, edst, g_msg, be_msg, E, invN);
    k4_update<<<444, 256>>>(goal, W_upd, b_upd, g_in, be_in, N, invN);
    k5_output<<<2960, 256>>>(W_out, b_out, g_upd, be_upd, out_u, out_o, N, invN);
}

// round 17
// speedup vs baseline: 1.4298x; 1.0605x over previous
#include <cuda_runtime.h>
#include <cuda_fp16.h>

#define NMAX 100000
#define EPS 1e-5f

typedef unsigned long long ull;

// ---------------- scratch ----------------
__device__ float g_buf_h[(size_t)NMAX * 64];   // h_raw (ReLU output, pre-BN)
__device__ float g_buf_m[(size_t)NMAX * 32];   // m_raw (pre-BN)
__device__ float g_agg  [(size_t)NMAX * 32];   // segment-sum of BN(m)
__device__ float g_buf_u[(size_t)NMAX * 64];   // u_raw
// [0:64) sum_h [64:128) sq_h [128:160) sum_m [192:224) sq_m [256:320) sum_u [320:384) sq_u
__device__ float g_stats[384];

// ---------------- f32x2 helpers ----------------
__device__ __forceinline__ void ffma2(ull &d, ull a, ull b) {
    asm("fma.rn.f32x2 %0, %1, %2, %0;" : "+l"(d) : "l"(a), "l"(b));
}
__device__ __forceinline__ ull dup2(float w) {
    ull r; unsigned u = __float_as_uint(w);
    asm("mov.b64 %0, {%1, %1};" : "=l"(r) : "r"(u)); return r;
}
__device__ __forceinline__ float2 unp2(ull v) {
    unsigned lo, hi;
    asm("mov.b64 {%0, %1}, %2;" : "=r"(lo), "=r"(hi) : "l"(v));
    return make_float2(__uint_as_float(lo), __uint_as_float(hi));
}
__device__ __forceinline__ unsigned h2u(__half2 h) {
    return *reinterpret_cast<unsigned*>(&h);
}

// ---------------- K0: zero agg + stats ----------------
__global__ __launch_bounds__(256) void k_zero(int n4) {
    int t = blockIdx.x * 256 + threadIdx.x;
    float4 z = make_float4(0.f, 0.f, 0.f, 0.f);
    if (t < n4) reinterpret_cast<float4*>(g_agg)[t] = z;
    if (t < 384) g_stats[t] = 0.f;
}

// ---------------- K1 (frozen): h_raw = ReLU(nodes @ W_in + b), h stats ------------
__global__ __launch_bounds__(256) void k1_input(
    const float* __restrict__ nodes, const float* __restrict__ W,
    const float* __restrict__ b, int Nn)
{
    __shared__ float sWt[32 * 64];
    __shared__ ulonglong2 sX[32 * 17];
    __shared__ float rs[64], rq[64];
    int tid = threadIdx.x;
    for (int i = tid; i < 2048; i += 256) sWt[i] = W[i];
    if (tid < 64) { rs[tid] = 0.f; rq[tid] = 0.f; }
    int c = tid & 31, wp = tid >> 5;
    ull bl = dup2(b[c]), bh = dup2(b[c + 32]);
    float s0 = 0.f, q0 = 0.f, s1 = 0.f, q1 = 0.f;
    float* sXf = (float*)sX;

    for (int tile = blockIdx.x * 64; tile < Nn; tile += gridDim.x * 64) {
        __syncthreads();
        int cnt = Nn - tile; if (cnt > 64) cnt = 64;
        for (int i = tid; i < 64 * 32; i += 256) {
            int n = i >> 5, k = i & 31;
            float v = (n < cnt) ? nodes[(size_t)(tile + n) * 32 + k] : 0.f;
            sXf[(n >> 1) * 68 + k * 2 + (n & 1)] = v;
        }
        __syncthreads();

        ull a0[4], a1[4];
        #pragma unroll
        for (int p = 0; p < 4; p++) { a0[p] = bl; a1[p] = bh; }
        #pragma unroll
        for (int k2 = 0; k2 < 16; k2++) {
            int k = k2 * 2;
            ull w0 = dup2(sWt[k * 64 + c]);
            ull w1 = dup2(sWt[k * 64 + c + 32]);
            ull w2 = dup2(sWt[k * 64 + 64 + c]);
            ull w3 = dup2(sWt[k * 64 + 64 + c + 32]);
            #pragma unroll
            for (int p = 0; p < 4; p++) {
                ulonglong2 x = sX[(wp * 4 + p) * 17 + k2];
                ffma2(a0[p], x.x, w0); ffma2(a1[p], x.x, w1);
                ffma2(a0[p], x.y, w2); ffma2(a1[p], x.y, w3);
            }
        }
        #pragma unroll
        for (int p = 0; p < 4; p++) {
            float2 f0 = unp2(a0[p]), f1 = unp2(a1[p]);
            int n0 = tile + wp * 8 + 2 * p;
            float v;
            if (n0 < Nn) {
                v = fmaxf(f0.x, 0.f); g_buf_h[(size_t)n0 * 64 + c] = v;        s0 += v; q0 += v * v;
                v = fmaxf(f1.x, 0.f); g_buf_h[(size_t)n0 * 64 + c + 32] = v;   s1 += v; q1 += v * v;
            }
            if (n0 + 1 < Nn) {
                v = fmaxf(f0.y, 0.f); g_buf_h[(size_t)(n0 + 1) * 64 + c] = v;      s0 += v; q0 += v * v;
                v = fmaxf(f1.y, 0.f); g_buf_h[(size_t)(n0 + 1) * 64 + c + 32] = v; s1 += v; q1 += v * v;
            }
        }
    }
    __syncthreads();
    atomicAdd(&rs[c], s0);      atomicAdd(&rq[c], q0);
    atomicAdd(&rs[c + 32], s1); atomicAdd(&rq[c + 32], q1);
    __syncthreads();
    if (tid < 64) { atomicAdd(&g_stats[tid], rs[tid]); atomicAdd(&g_stats[64 + tid], rq[tid]); }
}

// ---------------- K2 v3 (fp16 m16n8k16 mma): m_raw = ReLU(BN(h) @ W_msg + b) -------
// Tile 64 nodes x 32 ch; warp = (wp&3)*16 nodes x (wp>>2)*16 ch; 4 k-steps (K=64).
// A: half2 [node][kp] stride 36 (banks 4g+t, conflict-free).
// B: half2 [kp][c]    stride 40 (banks 8t+g, conflict-free).
__global__ __launch_bounds__(256) void k2_msg(
    const float* __restrict__ Wm, const float* __restrict__ bm,
    const float* __restrict__ gam, const float* __restrict__ bet,
    int Nn, float invN)
{
    __shared__ __align__(16) __half2 sW2[32 * 40];   // 5 KB  (W[2kp][c], W[2kp+1][c]) folded
    __shared__ __align__(16) __half2 sX2[64 * 36];   // 9 KB
    __shared__ float sSc[64], sSh[64], sB[32];
    __shared__ float rs[32], rq[32];
    int tid = threadIdx.x;
    if (tid < 64) {
        float mean = g_stats[tid] * invN;
        float var  = fmaf(-mean, mean, g_stats[64 + tid] * invN);
        float r = rsqrtf(var + EPS);
        float s = gam[tid] * r;
        sSc[tid] = s; sSh[tid] = bet[tid] - mean * s;
    }
    if (tid < 32) { sB[tid] = bm[tid]; rs[tid] = 0.f; rq[tid] = 0.f; }
    __syncthreads();
    for (int i = tid; i < 1024; i += 256) {
        int kp = i >> 5, cc = i & 31;
        float w0 = Wm[(2 * kp) * 32 + cc]     * sSc[2 * kp];
        float w1 = Wm[(2 * kp + 1) * 32 + cc] * sSc[2 * kp + 1];
        sW2[kp * 40 + cc] = __floats2half2_rn(w0, w1);
    }
    {
        int cc = tid & 31, part = tid >> 5;
        float acc = 0.f;
        #pragma unroll
        for (int j = part * 8; j < part * 8 + 8; j++) acc += sSh[j] * Wm[j * 32 + cc];
        atomicAdd(&sB[cc], acc);
    }
    __syncthreads();

    int lane = tid & 31, wp = tid >> 5;
    int g = lane >> 2, t = lane & 3;
    int mb = (wp & 3) * 16;
    int nb = (wp >> 2) * 16;
    float s_[2][2], q_[2][2];
    #pragma unroll
    for (int n = 0; n < 2; n++) { s_[n][0] = s_[n][1] = q_[n][0] = q_[n][1] = 0.f; }
    const float4* hp = (const float4*)g_buf_h;
    float4 z4 = make_float4(0.f, 0.f, 0.f, 0.f);
    const unsigned* sXu = (const unsigned*)sX2;
    const unsigned* sWu = (const unsigned*)sW2;

    for (int tile = blockIdx.x * 64; tile < Nn; tile += gridDim.x * 64) {
        __syncthreads();
        #pragma unroll
        for (int it = 0; it < 4; it++) {
            int f = tid + it * 256;            // 0..1023; node row = 16 float4
            int n = f >> 4, r = f & 15;
            int gn = tile + n;
            float4 v = (gn < Nn) ? hp[(size_t)gn * 16 + r] : z4;
            __half2 lo = __floats2half2_rn(v.x, v.y);
            __half2 hi = __floats2half2_rn(v.z, v.w);
            uint2 o = make_uint2(h2u(lo), h2u(hi));
            *reinterpret_cast<uint2*>(&sX2[n * 36 + 2 * r]) = o;
        }
        __syncthreads();

        float c0[2], c1[2], c2[2], c3[2];
        #pragma unroll
        for (int n = 0; n < 2; n++) {
            int ch = nb + 8 * n + 2 * t;
            c0[n] = sB[ch]; c1[n] = sB[ch + 1];
            c2[n] = c0[n];  c3[n] = c1[n];
        }
        #pragma unroll
        for (int ks = 0; ks < 4; ks++) {
            int k0 = ks * 8;                   // half2 units
            unsigned a0 = sXu[(mb + g)     * 36 + k0 + t];
            unsigned a1 = sXu[(mb + g + 8) * 36 + k0 + t];
            unsigned a2 = sXu[(mb + g)     * 36 + k0 + t + 4];
            unsigned a3 = sXu[(mb + g + 8) * 36 + k0 + t + 4];
            #pragma unroll
            for (int n = 0; n < 2; n++) {
                int ncol = nb + 8 * n + g;
                unsigned b0 = sWu[(k0 + t)     * 40 + ncol];
                unsigned b1 = sWu[(k0 + t + 4) * 40 + ncol];
                asm volatile(
                    "mma.sync.aligned.m16n8k16.row.col.f32.f16.f16.f32 "
                    "{%0,%1,%2,%3}, {%4,%5,%6,%7}, {%8,%9}, {%0,%1,%2,%3};"
                    : "+f"(c0[n]), "+f"(c1[n]), "+f"(c2[n]), "+f"(c3[n])
                    : "r"(a0), "r"(a1), "r"(a2), "r"(a3), "r"(b0), "r"(b1));
            }
        }
        int gn0 = tile + mb + g, gn1 = gn0 + 8;
        #pragma unroll
        for (int n = 0; n < 2; n++) {
            int ch = nb + 8 * n + 2 * t;
            if (gn0 < Nn) {
                float v0 = fmaxf(c0[n], 0.f), v1 = fmaxf(c1[n], 0.f);
                *reinterpret_cast<float2*>(&g_buf_m[(size_t)gn0 * 32 + ch]) = make_float2(v0, v1);
                s_[n][0] += v0; q_[n][0] += v0 * v0;
                s_[n][1] += v1; q_[n][1] += v1 * v1;
            }
            if (gn1 < Nn) {
                float v0 = fmaxf(c2[n], 0.f), v1 = fmaxf(c3[n], 0.f);
                *reinterpret_cast<float2*>(&g_buf_m[(size_t)gn1 * 32 + ch]) = make_float2(v0, v1);
                s_[n][0] += v0; q_[n][0] += v0 * v0;
                s_[n][1] += v1; q_[n][1] += v1 * v1;
            }
        }
    }
    __syncthreads();
    #pragma unroll
    for (int n = 0; n < 2; n++) {
        int ch = nb + 8 * n + 2 * t;
        atomicAdd(&rs[ch], s_[n][0]);     atomicAdd(&rq[ch], q_[n][0]);
        atomicAdd(&rs[ch + 1], s_[n][1]); atomicAdd(&rq[ch + 1], q_[n][1]);
    }
    __syncthreads();
    if (tid < 32) { atomicAdd(&g_stats[128 + tid], rs[tid]); atomicAdd(&g_stats[192 + tid], rq[tid]); }
}

// ---------------- K3 (frozen, ILP 8, at LTS ceiling): 8 edges / group --------------
__global__ __launch_bounds__(256) void k3_edges(
    const int* __restrict__ esrc, const int* __restrict__ edst,
    const float* __restrict__ gam, const float* __restrict__ bet,
    int E, float invN)
{
    __shared__ float sc[32], sh[32];
    if (threadIdx.x < 32) {
        int c = threadIdx.x;
        float mean = g_stats[128 + c] * invN;
        float var  = fmaf(-mean, mean, g_stats[192 + c] * invN);
        float r = rsqrtf(var + EPS);
        float s = gam[c] * r;
        sc[c] = s; sh[c] = bet[c] - mean * s;
    }
    __syncthreads();
    long long t = (long long)blockIdx.x * 256 + threadIdx.x;
    int g = (int)(t >> 3);
    int e0 = g * 8;
    if (e0 >= E) return;
    int j = (int)(t & 7);
    int c0 = j * 4;
    float scx = sc[c0], scy = sc[c0 + 1], scz = sc[c0 + 2], scw = sc[c0 + 3];
    float shx = sh[c0], shy = sh[c0 + 1], shz = sh[c0 + 2], shw = sh[c0 + 3];
    const float4* mp = (const float4*)g_buf_m;

    if (e0 + 8 <= E) {
        int4 sA = *(const int4*)(esrc + e0);
        int4 sB4 = *(const int4*)(esrc + e0 + 4);
        int4 dA = *(const int4*)(edst + e0);
        int4 dB = *(const int4*)(edst + e0 + 4);
        int ss[8] = {sA.x, sA.y, sA.z, sA.w, sB4.x, sB4.y, sB4.z, sB4.w};
        int dd[8] = {dA.x, dA.y, dA.z, dA.w, dB.x, dB.y, dB.z, dB.w};
        float4 v[8];
        #pragma unroll
        for (int i = 0; i < 8; i++) v[i] = __ldg(mp + (size_t)ss[i] * 8 + j);
        #pragma unroll
        for (int i = 0; i < 8; i++) {
            float x = fmaf(v[i].x, scx, shx), y = fmaf(v[i].y, scy, shy);
            float z = fmaf(v[i].z, scz, shz), w = fmaf(v[i].w, scw, shw);
            float* p = g_agg + (size_t)dd[i] * 32 + c0;
            asm volatile("red.global.add.v4.f32 [%0], {%1,%2,%3,%4};"
                         :: "l"(p), "f"(x), "f"(y), "f"(z), "f"(w) : "memory");
        }
    } else {
        for (int e = e0; e < E; e++) {
            int s = esrc[e], d = edst[e];
            float4 v = __ldg(mp + (size_t)s * 8 + j);
            float x = fmaf(v.x, scx, shx), y = fmaf(v.y, scy, shy);
            float z = fmaf(v.z, scz, shz), w = fmaf(v.w, scw, shw);
            float* p = g_agg + (size_t)d * 32 + c0;
            asm volatile("red.global.add.v4.f32 [%0], {%1,%2,%3,%4};"
                         :: "l"(p), "f"(x), "f"(y), "f"(z), "f"(w) : "memory");
        }
    }
}

// ---------------- K4 v4 (fp16 m16n8k16 mma): u_raw = ReLU([agg,BN(h),goal]@W + b) --
// Tile 64 nodes x 64 ch; warp = (wp&3)*16 nodes x (wp>>2)*32 ch; 7 k-steps (K=112).
// A: half2 [node][kp] stride 60 (banks 28g+t, conflict-free).
// B: half2 [kp][c]    stride 72 (banks 8t+g, conflict-free).
__global__ __launch_bounds__(256) void k4_update(
    const float* __restrict__ goal, const float* __restrict__ Wu,
    const float* __restrict__ bu, const float* __restrict__ gam,
    const float* __restrict__ bet, int Nn, float invN)
{
    __shared__ __align__(16) __half2 sW2[56 * 72];   // 15.75 KB folded (k-pairs)
    __shared__ __align__(16) __half2 sX2[64 * 60];   // 15.0 KB
    __shared__ float sSc[64], sSh[64], sB[64];
    __shared__ float rs[64], rq[64];
    int tid = threadIdx.x;
    if (tid < 64) {
        float mean = g_stats[tid] * invN;
        float var  = fmaf(-mean, mean, g_stats[64 + tid] * invN);
        float r = rsqrtf(var + EPS);
        float s = gam[tid] * r;
        sSc[tid] = s; sSh[tid] = bet[tid] - mean * s;
        sB[tid] = bu[tid]; rs[tid] = 0.f; rq[tid] = 0.f;
    }
    __syncthreads();
    for (int i = tid; i < 56 * 64; i += 256) {
        int kp = i >> 6, cc = i & 63;
        int k0 = 2 * kp, k1i = 2 * kp + 1;
        float f0 = (k0  >= 32 && k0  < 96) ? sSc[k0  - 32] : 1.f;
        float f1 = (k1i >= 32 && k1i < 96) ? sSc[k1i - 32] : 1.f;
        sW2[kp * 72 + cc] = __floats2half2_rn(Wu[k0 * 64 + cc] * f0,
                                              Wu[k1i * 64 + cc] * f1);
    }
    {
        int cc = tid & 63, part = tid >> 6;
        float acc = 0.f;
        #pragma unroll
        for (int j = part * 16; j < part * 16 + 16; j++) acc += sSh[j] * Wu[(32 + j) * 64 + cc];
        atomicAdd(&sB[cc], acc);
    }
    __syncthreads();

    int lane = tid & 31, wp = tid >> 5;
    int g = lane >> 2, t = lane & 3;
    int mb = (wp & 3) * 16;       // m-strip base node (in tile)
    int nb = (wp >> 2) * 32;      // n-half base channel
    float s_[4][2], q_[4][2];
    #pragma unroll
    for (int n = 0; n < 4; n++) { s_[n][0] = s_[n][1] = q_[n][0] = q_[n][1] = 0.f; }
    const float4* ap = (const float4*)g_agg;
    const float4* hp = (const float4*)g_buf_h;
    const float4* gp = (const float4*)goal;
    float4 z4 = make_float4(0.f, 0.f, 0.f, 0.f);
    const unsigned* sXu = (const unsigned*)sX2;
    const unsigned* sWu = (const unsigned*)sW2;

    for (int tile = blockIdx.x * 64; tile < Nn; tile += gridDim.x * 64) {
        __syncthreads();
        #pragma unroll
        for (int it = 0; it < 7; it++) {
            int f = tid + it * 256;            // 0..1791; node row = 28 float4
            int n = f / 28, r = f - n * 28;
            int gn = tile + n;
            float4 v = z4;
            if (gn < Nn) {
                v = (r < 8)  ? ap[(size_t)gn * 8 + r]
                  : (r < 24) ? hp[(size_t)gn * 16 + (r - 8)]
                             : gp[(size_t)gn * 4 + (r - 24)];
            }
            __half2 lo = __floats2half2_rn(v.x, v.y);
            __half2 hi = __floats2half2_rn(v.z, v.w);
            uint2 o = make_uint2(h2u(lo), h2u(hi));
            *reinterpret_cast<uint2*>(&sX2[n * 60 + 2 * r]) = o;
        }
        __syncthreads();

        float c0[4], c1[4], c2[4], c3[4];
        #pragma unroll
        for (int n = 0; n < 4; n++) {
            int ch = nb + 8 * n + 2 * t;
            c0[n] = sB[ch]; c1[n] = sB[ch + 1];
            c2[n] = c0[n];  c3[n] = c1[n];
        }
        #pragma unroll
        for (int ks = 0; ks < 7; ks++) {
            int k0 = ks * 8;                   // half2 units
            unsigned a0 = sXu[(mb + g)     * 60 + k0 + t];
            unsigned a1 = sXu[(mb + g + 8) * 60 + k0 + t];
            unsigned a2 = sXu[(mb + g)     * 60 + k0 + t + 4];
            unsigned a3 = sXu[(mb + g + 8) * 60 + k0 + t + 4];
            #pragma unroll
            for (int n = 0; n < 4; n++) {
                int ncol = nb + 8 * n + g;
                unsigned b0 = sWu[(k0 + t)     * 72 + ncol];
                unsigned b1 = sWu[(k0 + t + 4) * 72 + ncol];
                asm volatile(
                    "mma.sync.aligned.m16n8k16.row.col.f32.f16.f16.f32 "
                    "{%0,%1,%2,%3}, {%4,%5,%6,%7}, {%8,%9}, {%0,%1,%2,%3};"
                    : "+f"(c0[n]), "+f"(c1[n]), "+f"(c2[n]), "+f"(c3[n])
                    : "r"(a0), "r"(a1), "r"(a2), "r"(a3), "r"(b0), "r"(b1));
            }
        }
        int gn0 = tile + mb + g, gn1 = gn0 + 8;
        #pragma unroll
        for (int n = 0; n < 4; n++) {
            int ch = nb + 8 * n + 2 * t;
            if (gn0 < Nn) {
                float v0 = fmaxf(c0[n], 0.f), v1 = fmaxf(c1[n], 0.f);
                *reinterpret_cast<float2*>(&g_buf_u[(size_t)gn0 * 64 + ch]) = make_float2(v0, v1);
                s_[n][0] += v0; q_[n][0] += v0 * v0;
                s_[n][1] += v1; q_[n][1] += v1 * v1;
            }
            if (gn1 < Nn) {
                float v0 = fmaxf(c2[n], 0.f), v1 = fmaxf(c3[n], 0.f);
                *reinterpret_cast<float2*>(&g_buf_u[(size_t)gn1 * 64 + ch]) = make_float2(v0, v1);
                s_[n][0] += v0; q_[n][0] += v0 * v0;
                s_[n][1] += v1; q_[n][1] += v1 * v1;
            }
        }
    }
    __syncthreads();
    #pragma unroll
    for (int n = 0; n < 4; n++) {
        int ch = nb + 8 * n + 2 * t;
        atomicAdd(&rs[ch], s_[n][0]);     atomicAdd(&rq[ch], q_[n][0]);
        atomicAdd(&rs[ch + 1], s_[n][1]); atomicAdd(&rq[ch + 1], q_[n][1]);
    }
    __syncthreads();
    if (tid < 64) { atomicAdd(&g_stats[256 + tid], rs[tid]); atomicAdd(&g_stats[320 + tid], rq[tid]); }
}

// ---------------- K5 (frozen, vectorized + stride-68 weights) ----------------------
__global__ __launch_bounds__(256) void k5_output(
    const float* __restrict__ Wo, const float* __restrict__ bo,
    const float* __restrict__ gam, const float* __restrict__ bet,
    float* __restrict__ out_u, float* __restrict__ out_o,
    int Nn, float invN)
{
    __shared__ __align__(16) float sWt[8 * 68];   // transposed [oc][k], stride 68
    __shared__ __align__(16) float sU[4 * 68];
    __shared__ float sScale[64], sShift[64];
    int tid = threadIdx.x;
    for (int i = tid; i < 512; i += 256) {
        int k = i >> 3, oc = i & 7;
        sWt[oc * 68 + k] = Wo[i];
    }
    if (tid < 64) {
        float mean = g_stats[256 + tid] * invN;
        float var  = fmaf(-mean, mean, g_stats[320 + tid] * invN);
        float r    = rsqrtf(var + EPS);
        float sc   = gam[tid] * r;
        sScale[tid] = sc; sShift[tid] = bet[tid] - mean * sc;
    }
    int c = tid & 63, l = tid >> 6;

    for (int base = blockIdx.x * 4; base < Nn; base += gridDim.x * 4) {
        __syncthreads();
        int n = base + l;
        float u = 0.f;
        if (n < Nn) {
            u = fmaf(g_buf_u[(size_t)n * 64 + c], sScale[c], sShift[c]);
            out_u[(size_t)n * 64 + c] = u;
        }
        sU[l * 68 + c] = u;
        __syncthreads();
        if (tid < 32) {
            int ln = tid >> 3, oc = tid & 7;
            int nn = base + ln;
            if (nn < Nn) {
                float acc = bo[oc];
                #pragma unroll
                for (int kk = 0; kk < 16; kk++) {
                    float4 uv = *reinterpret_cast<const float4*>(&sU[ln * 68 + kk * 4]);
                    float4 wv = *reinterpret_cast<const float4*>(&sWt[oc * 68 + kk * 4]);
                    acc = fmaf(uv.x, wv.x, acc); acc = fmaf(uv.y, wv.y, acc);
                    acc = fmaf(uv.z, wv.z, acc); acc = fmaf(uv.w, wv.w, acc);
                }
                out_o[(size_t)nn * 8 + oc] = acc;
            }
        }
    }
}

// ---------------- host launcher ----------------
extern "C" void kernel_launch(void* const* d_in, const int* in_sizes, int n_in,
                              void* d_out, int out_size)
{
    const float* nodes  = (const float*)d_in[0];
    const float* goal   = (const float*)d_in[1];
    const int*   esrc   = (const int*)d_in[2];
    const int*   edst   = (const int*)d_in[3];
    const float* W_in   = (const float*)d_in[6];
    const float* b_in   = (const float*)d_in[7];
    const float* g_in   = (const float*)d_in[8];
    const float* be_in  = (const float*)d_in[9];
    const float* W_msg  = (const float*)d_in[10];
    const float* b_msg  = (const float*)d_in[11];
    const float* g_msg  = (const float*)d_in[12];
    const float* be_msg = (const float*)d_in[13];
    const float* W_upd  = (const float*)d_in[14];
    const float* b_upd  = (const float*)d_in[15];
    const float* g_upd  = (const float*)d_in[16];
    const float* be_upd = (const float*)d_in[17];
    const float* W_out  = (const float*)d_in[18];
    const float* b_out  = (const float*)d_in[19];

    int N = in_sizes[0] / 32;
    int E = in_sizes[2];
    float invN = 1.0f / (float)N;

    float* dout = (float*)d_out;
    float* out_u;
    float* out_o;
    if ((long long)out_size >= (long long)N * 72) {        // tuple (u, out) concatenated
        out_u = dout;
        out_o = dout + (size_t)N * 64;
    } else if ((long long)out_size == (long long)N * 8) {  // only `out`
        void* p; cudaGetSymbolAddress(&p, g_buf_h);
        out_u = (float*)p;  out_o = dout;
    } else {                                               // only `u`
        void* p; cudaGetSymbolAddress(&p, g_buf_h);
        out_u = dout;       out_o = (float*)p;
    }

    int n4 = N * 8;   // N*32/4 float4s of agg
    k_zero  <<<(n4 + 255) / 256, 256>>>(n4);
    k1_input<<<592, 256>>>(nodes, W_in, b_in, N);
    k2_msg  <<<592, 256>>>(W_msg, b_msg, g_in, be_in, N, invN);
    long long groups = ((long long)E + 7) / 8;
    long long thr = groups * 8;
    k3_edges<<<(int)((thr + 255) / 256), 256>>>(esrc, edst, g_msg, be_msg, E, invN);
    k4_update<<<592, 256>>>(goal, W_upd, b_upd, g_in, be_in, N, invN);
    k5_output<<<2960, 256>>>(W_out, b_out, g_upd, be_upd, out_u, out_o, N, invN);
}